// round 1
// baseline (speedup 1.0000x reference)
#include <cuda_runtime.h>
#include <math.h>

// ---------------------------------------------------------------------------
// Problem constants
// ---------------------------------------------------------------------------
namespace {
constexpr int kS = 48;          // source length
constexpr int kT = 32;          // target length
constexpr int kB = 64;          // batch
constexpr int kH = 1024;        // hidden
constexpr int kE = 512;         // embed
constexpr int kV = 32000;       // vocab
constexpr int kG = 3 * kH;      // 3072 gates
constexpr int kF = 3 * kH + kE; // 3584 out-proj features
constexpr int kXW = kE + 2*kH;  // 2560 decoder GRU input
constexpr int kPAD = 1;
}

// ---------------------------------------------------------------------------
// Persistent scratch (device globals -> no allocation inside kernel_launch)
// ---------------------------------------------------------------------------
__device__ float g_emb[(size_t)kS * kB * kE];        // encoder embeddings [s*B+b][E]
__device__ float g_gxf[(size_t)kS * kB * kG];        // fwd input gates    [s*B+b][3H]
__device__ float g_gxb[(size_t)kS * kB * kG];        // bwd input gates    [s*B+b][3H]
__device__ float g_enc[(size_t)kB * kS * 2 * kH];    // enc_bt             [b][s][2H]
__device__ float g_encproj[(size_t)kB * kS * kH];    // enc @ Wa2^T + b    [b][s][H]
__device__ float g_h[2 * kB * kH];                   // h_f | h_b
__device__ float g_gh[2 * kB * kG];                  // recurrent gates scratch
__device__ float g_hcat[kB * 2 * kH];                // [hf, hb]
__device__ float g_hdec[kB * kH];                    // decoder hidden
__device__ float g_hp[kB * kH];                      // h @ Wa1^T
__device__ float g_xw[kB * kXW];                     // [et, w]
__device__ float g_gxd[kB * kG];                     // decoder input gates
__device__ float g_ghd[kB * kG];                     // decoder recurrent gates
__device__ float g_feat[(size_t)(kT - 1) * kB * kF]; // [h2, w, et] per step

// ---------------------------------------------------------------------------
// init: zero timestep-0 of output and the encoder hidden states
// ---------------------------------------------------------------------------
__global__ void init_kernel(float* __restrict__ out0) {
    size_t i = (size_t)blockIdx.x * blockDim.x + threadIdx.x;
    if (i < (size_t)kB * kV) out0[i] = 0.f;
    if (i < (size_t)2 * kB * kH) g_h[i] = 0.f;
}

// ---------------------------------------------------------------------------
// encoder embedding gather: g_emb[s*B+b][:] = emb_enc[src[s*B+b]][:]
// ---------------------------------------------------------------------------
__global__ void enc_embed_kernel(const int* __restrict__ src,
                                 const float* __restrict__ table) {
    int row = blockIdx.x;                 // s*B + b
    int tok = src[row];
    const float4* sp = (const float4*)(table + (size_t)tok * kE);
    float4* dp = (float4*)(g_emb + (size_t)row * kE);
    dp[threadIdx.x] = sp[threadIdx.x];    // 128 thr * float4 = 512 floats
}

// ---------------------------------------------------------------------------
// Generic SGEMM:  C[M,N] = A[M,K] * B[N,K]^T + bias[N]   (TN form, K contig)
// 128x128x16 tiles, 256 threads, 8x8 per-thread microtile.
// act: 0 = none, 1 = tanh
// ---------------------------------------------------------------------------
__global__ __launch_bounds__(256)
void sgemm_tn(const float* __restrict__ A, int lda,
              const float* __restrict__ Bm, int ldb,
              const float* __restrict__ bias,
              float* __restrict__ C, int ldc,
              int M, int N, int K, int act) {
    constexpr int BM = 128, BN = 128, BK = 16;
    __shared__ __align__(16) float As[BK][BM];
    __shared__ __align__(16) float Bs[BK][BN];
    const int tid = threadIdx.x;
    const int bm = blockIdx.y * BM;
    const int bn = blockIdx.x * BN;
    const int lr = tid >> 2;           // 0..63
    const int lc = (tid & 3) << 2;     // 0,4,8,12
    const int tm = (tid >> 4) << 3;    // 0..120
    const int tn = (tid & 15) << 3;    // 0..120

    float acc[8][8];
#pragma unroll
    for (int i = 0; i < 8; i++)
#pragma unroll
        for (int j = 0; j < 8; j++) acc[i][j] = 0.f;

    for (int k0 = 0; k0 < K; k0 += BK) {
#pragma unroll
        for (int h = 0; h < 2; h++) {
            int r = lr + h * 64;
            int gr = bm + r;
            float4 v = make_float4(0.f, 0.f, 0.f, 0.f);
            if (gr < M) v = *(const float4*)(A + (size_t)gr * lda + k0 + lc);
            As[lc + 0][r] = v.x; As[lc + 1][r] = v.y;
            As[lc + 2][r] = v.z; As[lc + 3][r] = v.w;
            int gc = bn + r;
            float4 w = make_float4(0.f, 0.f, 0.f, 0.f);
            if (gc < N) w = *(const float4*)(Bm + (size_t)gc * ldb + k0 + lc);
            Bs[lc + 0][r] = w.x; Bs[lc + 1][r] = w.y;
            Bs[lc + 2][r] = w.z; Bs[lc + 3][r] = w.w;
        }
        __syncthreads();
#pragma unroll
        for (int k = 0; k < BK; k++) {
            float a[8], b[8];
            *(float4*)&a[0] = *(const float4*)&As[k][tm];
            *(float4*)&a[4] = *(const float4*)&As[k][tm + 4];
            *(float4*)&b[0] = *(const float4*)&Bs[k][tn];
            *(float4*)&b[4] = *(const float4*)&Bs[k][tn + 4];
#pragma unroll
            for (int i = 0; i < 8; i++)
#pragma unroll
                for (int j = 0; j < 8; j++)
                    acc[i][j] = fmaf(a[i], b[j], acc[i][j]);
        }
        __syncthreads();
    }
#pragma unroll
    for (int i = 0; i < 8; i++) {
        int row = bm + tm + i;
        if (row < M) {
#pragma unroll
            for (int j = 0; j < 8; j++) {
                int col = bn + tn + j;
                if (col < N) {
                    float v = acc[i][j] + (bias ? bias[col] : 0.f);
                    if (act == 1) v = tanhf(v);
                    C[(size_t)row * ldc + col] = v;
                }
            }
        }
    }
}

// ---------------------------------------------------------------------------
// Small-M GEMM: M = 64 fixed (batch), 64-wide N tiles, BK = 32, 4x4 microtile.
// Requires N % 64 == 0, K % 32 == 0 (holds for all call sites).
// ---------------------------------------------------------------------------
__device__ __forceinline__
void gemm64_body(const float* __restrict__ A, int lda,
                 const float* __restrict__ Bm, int ldb,
                 const float* __restrict__ bias,
                 float* __restrict__ C, int ldc,
                 int K, int act, int nb) {
    constexpr int BK = 32;
    __shared__ __align__(16) float As[BK][64];
    __shared__ __align__(16) float Bs[BK][64];
    const int tid = threadIdx.x;
    const int bn = nb * 64;
    const int lr = tid >> 3;          // 0..31
    const int lc = (tid & 7) << 2;    // 0..28 step 4
    const int tm = (tid >> 4) << 2;   // 0..60
    const int tn = (tid & 15) << 2;   // 0..60

    float acc[4][4];
#pragma unroll
    for (int i = 0; i < 4; i++)
#pragma unroll
        for (int j = 0; j < 4; j++) acc[i][j] = 0.f;

    for (int k0 = 0; k0 < K; k0 += BK) {
#pragma unroll
        for (int h = 0; h < 2; h++) {
            int r = lr + h * 32;
            float4 v = *(const float4*)(A + (size_t)r * lda + k0 + lc);
            As[lc + 0][r] = v.x; As[lc + 1][r] = v.y;
            As[lc + 2][r] = v.z; As[lc + 3][r] = v.w;
            float4 w = *(const float4*)(Bm + (size_t)(bn + r) * ldb + k0 + lc);
            Bs[lc + 0][r] = w.x; Bs[lc + 1][r] = w.y;
            Bs[lc + 2][r] = w.z; Bs[lc + 3][r] = w.w;
        }
        __syncthreads();
#pragma unroll
        for (int k = 0; k < BK; k++) {
            float a[4], b[4];
            *(float4*)&a[0] = *(const float4*)&As[k][tm];
            *(float4*)&b[0] = *(const float4*)&Bs[k][tn];
#pragma unroll
            for (int i = 0; i < 4; i++)
#pragma unroll
                for (int j = 0; j < 4; j++)
                    acc[i][j] = fmaf(a[i], b[j], acc[i][j]);
        }
        __syncthreads();
    }
#pragma unroll
    for (int i = 0; i < 4; i++) {
#pragma unroll
        for (int j = 0; j < 4; j++) {
            int col = bn + tn + j;
            float v = acc[i][j] + (bias ? bias[col] : 0.f);
            if (act == 1) v = tanhf(v);
            C[(size_t)(tm + i) * ldc + col] = v;
        }
    }
}

__global__ __launch_bounds__(256)
void gemm64(const float* __restrict__ A, int lda,
            const float* __restrict__ Bm, int ldb,
            const float* __restrict__ bias,
            float* __restrict__ C, int ldc, int K, int act) {
    gemm64_body(A, lda, Bm, ldb, bias, C, ldc, K, act, blockIdx.x);
}

// Encoder recurrent GEMM, both directions in one launch (blockIdx.z selects)
__global__ __launch_bounds__(256)
void gemm64_dual(const float* __restrict__ A0, const float* __restrict__ B0,
                 const float* __restrict__ b0, float* __restrict__ C0,
                 const float* __restrict__ A1, const float* __restrict__ B1,
                 const float* __restrict__ b1, float* __restrict__ C1,
                 int lda, int ldb, int ldc, int K) {
    if (blockIdx.z == 0)
        gemm64_body(A0, lda, B0, ldb, b0, C0, ldc, K, 0, blockIdx.x);
    else
        gemm64_body(A1, lda, B1, ldb, b1, C1, ldc, K, 0, blockIdx.x);
}

// ---------------------------------------------------------------------------
// GRU gate update (encoder, both directions). s = time step.
// Fwd: gx = g_gxf[s], writes enc[b][s][0:H].
// Bwd: gx = g_gxb[S-1-s], writes enc[b][S-1-s][H:2H].
// ---------------------------------------------------------------------------
__global__ void gru_gate_enc(int s) {
    int idx = blockIdx.x * blockDim.x + threadIdx.x;
    if (idx >= 2 * kB * kH) return;
    int dir = idx / (kB * kH);
    int rem = idx - dir * kB * kH;
    int b = rem / kH, j = rem - b * kH;
    int gpos = dir ? (kS - 1 - s) : s;
    const float* gx = (dir ? g_gxb : g_gxf) + ((size_t)gpos * kB + b) * kG;
    const float* gh = g_gh + ((size_t)dir * kB + b) * kG;
    float* hvec = g_h + ((size_t)dir * kB + b) * kH;
    float h = hvec[j];
    float r = 1.f / (1.f + expf(-(gx[j] + gh[j])));
    float z = 1.f / (1.f + expf(-(gx[kH + j] + gh[kH + j])));
    float n = tanhf(gx[2 * kH + j] + r * gh[2 * kH + j]);
    float h2 = (1.f - z) * n + z * h;
    hvec[j] = h2;
    g_enc[((size_t)b * kS + gpos) * (2 * kH) + dir * kH + j] = h2;
}

// hcat[b][:] = [h_f[b], h_b[b]]
__global__ void hcat_kernel() {
    int idx = blockIdx.x * blockDim.x + threadIdx.x;
    if (idx >= 2 * kB * kH) return;
    int dir = idx / (kB * kH);
    int rem = idx - dir * kB * kH;
    int b = rem / kH, j = rem - b * kH;
    g_hcat[(size_t)b * 2 * kH + dir * kH + j] = g_h[idx];
}

// ---------------------------------------------------------------------------
// decoder embedding: et -> g_xw[b][0:E] and feat_t[b][3H:3H+E]
// ---------------------------------------------------------------------------
__global__ void dec_embed_kernel(const int* __restrict__ trg_t,
                                 const float* __restrict__ emb_dec,
                                 float* __restrict__ feat_t) {
    int b = blockIdx.x;
    int tok = trg_t[b];
    float4 v = ((const float4*)(emb_dec + (size_t)tok * kE))[threadIdx.x];
    ((float4*)(g_xw + (size_t)b * kXW))[threadIdx.x] = v;
    ((float4*)(feat_t + (size_t)b * kF + 3 * kH))[threadIdx.x] = v;
}

// ---------------------------------------------------------------------------
// Fused attention: scores (tanh energy . v_attn) -> mask -> softmax ->
// context w = a @ enc.  Writes w into g_xw[b][E:] and feat_t[b][H:3H].
// One block per batch element b, 256 threads.
// ---------------------------------------------------------------------------
__global__ __launch_bounds__(256)
void attn_kernel(const int* __restrict__ src,
                 const float* __restrict__ v_attn,
                 float* __restrict__ feat_t) {
    int b = blockIdx.x;
    __shared__ float sc[kS];
    int tid = threadIdx.x, warp = tid >> 5, lane = tid & 31;
    const float* hp = g_hp + (size_t)b * kH;

    for (int s = warp; s < kS; s += 8) {
        const float* ep = g_encproj + ((size_t)b * kS + s) * kH;
        float p = 0.f;
        for (int j = lane; j < kH; j += 32)
            p += v_attn[j] * tanhf(hp[j] + ep[j]);
#pragma unroll
        for (int o = 16; o; o >>= 1) p += __shfl_xor_sync(0xffffffffu, p, o);
        if (lane == 0) sc[s] = (src[s * kB + b] != kPAD) ? p : -1e10f;
    }
    __syncthreads();

    if (tid < 32) {
        float v1 = sc[tid];
        float v2 = (tid + 32 < kS) ? sc[tid + 32] : -1e30f;
        float mx = fmaxf(v1, v2);
#pragma unroll
        for (int o = 16; o; o >>= 1) mx = fmaxf(mx, __shfl_xor_sync(0xffffffffu, mx, o));
        float e1 = expf(v1 - mx);
        float e2 = (tid + 32 < kS) ? expf(v2 - mx) : 0.f;
        float sm = e1 + e2;
#pragma unroll
        for (int o = 16; o; o >>= 1) sm += __shfl_xor_sync(0xffffffffu, sm, o);
        float inv = 1.f / sm;
        sc[tid] = e1 * inv;
        if (tid + 32 < kS) sc[tid + 32] = e2 * inv;
    }
    __syncthreads();

    for (int c = tid; c < 2 * kH; c += 256) {
        float acc = 0.f;
#pragma unroll 8
        for (int s = 0; s < kS; s++)
            acc += sc[s] * g_enc[((size_t)b * kS + s) * (2 * kH) + c];
        g_xw[(size_t)b * kXW + kE + c] = acc;
        feat_t[(size_t)b * kF + kH + c] = acc;
    }
}

// decoder GRU gate: h2 -> g_hdec and feat_t[b][0:H]
__global__ void gru_gate_dec(float* __restrict__ feat_t) {
    int idx = blockIdx.x * blockDim.x + threadIdx.x;
    if (idx >= kB * kH) return;
    int b = idx / kH, j = idx - b * kH;
    const float* gx = g_gxd + (size_t)b * kG;
    const float* gh = g_ghd + (size_t)b * kG;
    float h = g_hdec[idx];
    float r = 1.f / (1.f + expf(-(gx[j] + gh[j])));
    float z = 1.f / (1.f + expf(-(gx[kH + j] + gh[kH + j])));
    float n = tanhf(gx[2 * kH + j] + r * gh[2 * kH + j]);
    float h2 = (1.f - z) * n + z * h;
    g_hdec[idx] = h2;
    feat_t[(size_t)b * kF + j] = h2;
}

// ---------------------------------------------------------------------------
// Host orchestration (graph-capturable: kernel launches only)
// ---------------------------------------------------------------------------
extern "C" void kernel_launch(void* const* d_in, const int* in_sizes, int n_in,
                              void* d_out, int out_size) {
    const int*   src     = (const int*)d_in[0];
    const int*   trg     = (const int*)d_in[1];
    const float* emb_enc = (const float*)d_in[2];
    const float* Wi_f    = (const float*)d_in[3];
    const float* Wh_f    = (const float*)d_in[4];
    const float* bi_f    = (const float*)d_in[5];
    const float* bh_f    = (const float*)d_in[6];
    const float* Wi_b    = (const float*)d_in[7];
    const float* Wh_b    = (const float*)d_in[8];
    const float* bi_b    = (const float*)d_in[9];
    const float* bh_b    = (const float*)d_in[10];
    const float* W_fc    = (const float*)d_in[11];
    const float* b_fc    = (const float*)d_in[12];
    const float* W_attn  = (const float*)d_in[13];
    const float* b_attn  = (const float*)d_in[14];
    const float* v_attn  = (const float*)d_in[15];
    const float* emb_dec = (const float*)d_in[16];
    const float* Wi_d    = (const float*)d_in[17];
    const float* Wh_d    = (const float*)d_in[18];
    const float* bi_d    = (const float*)d_in[19];
    const float* bh_d    = (const float*)d_in[20];
    const float* W_out   = (const float*)d_in[21];
    const float* b_out   = (const float*)d_in[22];
    float* out = (float*)d_out;

    float *p_emb, *p_gxf, *p_gxb, *p_enc, *p_ep, *p_h, *p_gh, *p_hcat,
          *p_hdec, *p_hp, *p_xw, *p_gxd, *p_ghd, *p_feat;
    cudaGetSymbolAddress((void**)&p_emb, g_emb);
    cudaGetSymbolAddress((void**)&p_gxf, g_gxf);
    cudaGetSymbolAddress((void**)&p_gxb, g_gxb);
    cudaGetSymbolAddress((void**)&p_enc, g_enc);
    cudaGetSymbolAddress((void**)&p_ep, g_encproj);
    cudaGetSymbolAddress((void**)&p_h, g_h);
    cudaGetSymbolAddress((void**)&p_gh, g_gh);
    cudaGetSymbolAddress((void**)&p_hcat, g_hcat);
    cudaGetSymbolAddress((void**)&p_hdec, g_hdec);
    cudaGetSymbolAddress((void**)&p_hp, g_hp);
    cudaGetSymbolAddress((void**)&p_xw, g_xw);
    cudaGetSymbolAddress((void**)&p_gxd, g_gxd);
    cudaGetSymbolAddress((void**)&p_ghd, g_ghd);
    cudaGetSymbolAddress((void**)&p_feat, g_feat);

    // 0. zero output timestep 0 + encoder hidden
    init_kernel<<<((size_t)kB * kV + 255) / 256, 256>>>(out);

    // 1. encoder embedding gather
    enc_embed_kernel<<<kS * kB, 128>>>(src, emb_enc);

    // 2. encoder input-gate GEMMs (batched over all timesteps)
    {
        dim3 g(kG / 128, (kS * kB) / 128);
        sgemm_tn<<<g, 256>>>(p_emb, kE, Wi_f, kE, bi_f, p_gxf, kG,
                             kS * kB, kG, kE, 0);
        sgemm_tn<<<g, 256>>>(p_emb, kE, Wi_b, kE, bi_b, p_gxb, kG,
                             kS * kB, kG, kE, 0);
    }

    // 3. encoder recurrence (fwd+bwd in parallel per step)
    for (int s = 0; s < kS; s++) {
        dim3 gd(kG / 64, 1, 2);
        gemm64_dual<<<gd, 256>>>(p_h, Wh_f, bh_f, p_gh,
                                 p_h + kB * kH, Wh_b, bh_b,
                                 p_gh + (size_t)kB * kG,
                                 kH, kH, kG, kH);
        gru_gate_enc<<<(2 * kB * kH) / 256, 256>>>(s);
    }

    // 4. decoder init hidden = tanh([hf,hb] @ W_fc^T + b_fc)
    hcat_kernel<<<(2 * kB * kH) / 256, 256>>>();
    gemm64<<<kH / 64, 256>>>(p_hcat, 2 * kH, W_fc, 2 * kH, b_fc,
                             p_hdec, kH, 2 * kH, 1);

    // 5. precompute encoder attention projection (b_attn folded in here)
    {
        dim3 g(kH / 128, (kB * kS) / 128);
        sgemm_tn<<<g, 256>>>(p_enc, 2 * kH, W_attn + kH, kG, b_attn,
                             p_ep, kH, kB * kS, kH, 2 * kH, 0);
    }

    // 6. decoder loop
    for (int t = 0; t < kT - 1; t++) {
        float* feat_t = p_feat + (size_t)t * kB * kF;
        dec_embed_kernel<<<kB, 128>>>(trg + (size_t)t * kB, emb_dec, feat_t);
        gemm64<<<kH / 64, 256>>>(p_hdec, kH, W_attn, kG, (const float*)nullptr,
                                 p_hp, kH, kH, 0);
        attn_kernel<<<kB, 256>>>(src, v_attn, feat_t);
        gemm64<<<kG / 64, 256>>>(p_xw, kXW, Wi_d, kXW, bi_d,
                                 p_gxd, kG, kXW, 0);
        gemm64<<<kG / 64, 256>>>(p_hdec, kH, Wh_d, kH, bh_d,
                                 p_ghd, kG, kH, 0);
        gru_gate_dec<<<(kB * kH) / 256, 256>>>(feat_t);
    }

    // 7. batched output projection for all timesteps at once
    {
        int M = (kT - 1) * kB; // 1984
        dim3 g(kV / 128, (M + 127) / 128);
        sgemm_tn<<<g, 256>>>(p_feat, kF, W_out, kF, b_out,
                             out + (size_t)kB * kV, kV, M, kV, kF, 0);
    }
}

// round 2
// speedup vs baseline: 2.0873x; 2.0873x over previous
#include <cuda_runtime.h>
#include <math.h>
#include <stdint.h>

// ---------------------------------------------------------------------------
// Problem constants
// ---------------------------------------------------------------------------
namespace {
constexpr int kS = 48;          // source length
constexpr int kT = 32;          // target length
constexpr int kB = 64;          // batch
constexpr int kH = 1024;        // hidden
constexpr int kE = 512;         // embed
constexpr int kV = 32000;       // vocab
constexpr int kG = 3 * kH;      // 3072 gates
constexpr int kF = 3 * kH + kE; // 3584 out-proj features
constexpr int kXW = kE + 2*kH;  // 2560 decoder GRU input width
constexpr int kPAD = 1;
}

// ---------------------------------------------------------------------------
// Packed fp32x2 helpers (sm_103a FFMA2 path — bit-exact fp32, 2x issue width)
// ---------------------------------------------------------------------------
__device__ __forceinline__ unsigned long long pk2(float x) {
    unsigned long long r;
    unsigned u = __float_as_uint(x);
    asm("mov.b64 %0, {%1, %1};" : "=l"(r) : "r"(u));
    return r;
}
__device__ __forceinline__ void fma2(unsigned long long& d,
                                     unsigned long long a,
                                     unsigned long long b) {
    asm("fma.rn.f32x2 %0, %1, %2, %0;" : "+l"(d) : "l"(a), "l"(b));
}
__device__ __forceinline__ float lo2(unsigned long long v) {
    return __uint_as_float((unsigned)v);
}
__device__ __forceinline__ float hi2(unsigned long long v) {
    return __uint_as_float((unsigned)(v >> 32));
}

// ---------------------------------------------------------------------------
// Persistent scratch (device globals -> no allocation inside kernel_launch)
// ---------------------------------------------------------------------------
__device__ float g_emb[(size_t)kS * kB * kE];        // encoder embeddings
__device__ float g_gxf[(size_t)kS * kB * kG];        // fwd input gates
__device__ float g_gxb[(size_t)kS * kB * kG];        // bwd input gates
__device__ float g_enc[(size_t)kB * kS * 2 * kH];    // enc_bt [b][s][2H]
__device__ float g_encproj[(size_t)kB * kS * kH];    // enc @ Wa2^T + b_attn
__device__ float g_h[2 * kB * kH];                   // h_f | h_b
__device__ float g_gh[4 * kB * kG];                  // enc recurrent partials [dir*2+ks]
__device__ float g_hcat[kB * 2 * kH];                // [hf, hb]
__device__ float g_hdec[kB * kH];                    // decoder hidden
__device__ float g_hp[kB * kH];                      // h @ Wa1^T
__device__ float g_w[kB * 2 * kH];                   // attention context
__device__ float g_gxp[2 * kB * kG];                 // decoder w-gate partials
__device__ float g_ghd[kB * kG];                     // decoder recurrent gates
__device__ float g_gxet[(size_t)(kT - 1) * kB * kG]; // et @ Wi_d[:, :E]^T + bi_d
__device__ float g_feat[(size_t)(kT - 1) * kB * kF]; // [h2, w, et] per step

// ---------------------------------------------------------------------------
// init: zero timestep-0 of output and the encoder hidden states
// ---------------------------------------------------------------------------
__global__ void init_kernel(float* __restrict__ out0) {
    size_t i = (size_t)blockIdx.x * blockDim.x + threadIdx.x;
    if (i < (size_t)kB * kV) out0[i] = 0.f;
    if (i < (size_t)2 * kB * kH) g_h[i] = 0.f;
}

// ---------------------------------------------------------------------------
// encoder embedding gather
// ---------------------------------------------------------------------------
__global__ void enc_embed_kernel(const int* __restrict__ src,
                                 const float* __restrict__ table) {
    int row = blockIdx.x;                 // s*B + b
    int tok = src[row];
    const float4* sp = (const float4*)(table + (size_t)tok * kE);
    float4* dp = (float4*)(g_emb + (size_t)row * kE);
    dp[threadIdx.x] = sp[threadIdx.x];
}

// decoder embeddings for all steps -> feat[t][b][3H:3H+E]
__global__ void dec_embed_all(const int* __restrict__ trg,
                              const float* __restrict__ emb_dec) {
    int row = blockIdx.x;                 // t*B + b, t in [0, T-1)
    int tok = trg[row];
    float4 v = ((const float4*)(emb_dec + (size_t)tok * kE))[threadIdx.x];
    ((float4*)(g_feat + (size_t)row * kF + 3 * kH))[threadIdx.x] = v;
}

// ---------------------------------------------------------------------------
// Large SGEMM: C[M,N] = A[M,K] * B[N,K]^T + bias[N], fp32x2 packed FMA.
// 128x256 tile, BK=16, 256 threads, 8x16 microtile (as 8x8 packed pairs).
// Requires N % 256 == 0, K % 16 == 0. M guarded.
// ---------------------------------------------------------------------------
__global__ __launch_bounds__(256, 1)
void sgemm_tn256(const float* __restrict__ A, int lda,
                 const float* __restrict__ Bm, int ldb,
                 const float* __restrict__ bias,
                 float* __restrict__ C, int ldc,
                 int M, int N, int K, int act) {
    constexpr int BM = 128, BN = 256, BK = 16;
    __shared__ __align__(16) float As[BK][BM];
    __shared__ __align__(16) float Bs[BK][BN];
    const int tid = threadIdx.x;
    const int bm = blockIdx.y * BM;
    const int bn = blockIdx.x * BN;
    const int lr = tid >> 2;            // 0..63
    const int lc = (tid & 3) << 2;      // 0,4,8,12
    const int tm = (tid >> 4) << 3;     // 0..120
    const int tn0 = (tid & 15) << 2;    // 0..60 ; columns tn0 + 64*c + {0..3}

    unsigned long long acc[8][8];
#pragma unroll
    for (int i = 0; i < 8; i++)
#pragma unroll
        for (int j = 0; j < 8; j++) acc[i][j] = 0ull;

    float4 ra[2], rb[4];
    // prefetch first k-tile into registers
    {
#pragma unroll
        for (int h = 0; h < 2; h++) {
            int gr = bm + lr + h * 64;
            ra[h] = (gr < M) ? *(const float4*)(A + (size_t)gr * lda + lc)
                             : make_float4(0.f, 0.f, 0.f, 0.f);
        }
#pragma unroll
        for (int h = 0; h < 4; h++) {
            int gc = bn + lr + h * 64;
            rb[h] = *(const float4*)(Bm + (size_t)gc * ldb + lc);
        }
    }

    for (int k0 = 0; k0 < K; k0 += BK) {
        // store prefetched tile to smem (transposed scatter)
#pragma unroll
        for (int h = 0; h < 2; h++) {
            int r = lr + h * 64;
            As[lc + 0][r] = ra[h].x; As[lc + 1][r] = ra[h].y;
            As[lc + 2][r] = ra[h].z; As[lc + 3][r] = ra[h].w;
        }
#pragma unroll
        for (int h = 0; h < 4; h++) {
            int r = lr + h * 64;
            Bs[lc + 0][r] = rb[h].x; Bs[lc + 1][r] = rb[h].y;
            Bs[lc + 2][r] = rb[h].z; Bs[lc + 3][r] = rb[h].w;
        }
        __syncthreads();

        // prefetch next tile while computing
        if (k0 + BK < K) {
            int kn = k0 + BK;
#pragma unroll
            for (int h = 0; h < 2; h++) {
                int gr = bm + lr + h * 64;
                ra[h] = (gr < M) ? *(const float4*)(A + (size_t)gr * lda + kn + lc)
                                 : make_float4(0.f, 0.f, 0.f, 0.f);
            }
#pragma unroll
            for (int h = 0; h < 4; h++) {
                int gc = bn + lr + h * 64;
                rb[h] = *(const float4*)(Bm + (size_t)gc * ldb + kn + lc);
            }
        }

#pragma unroll
        for (int k = 0; k < BK; k++) {
            float4 a0 = *(const float4*)&As[k][tm];
            float4 a1 = *(const float4*)&As[k][tm + 4];
            unsigned long long aa[8];
            aa[0] = pk2(a0.x); aa[1] = pk2(a0.y);
            aa[2] = pk2(a0.z); aa[3] = pk2(a0.w);
            aa[4] = pk2(a1.x); aa[5] = pk2(a1.y);
            aa[6] = pk2(a1.z); aa[7] = pk2(a1.w);
            unsigned long long bb[8];
#pragma unroll
            for (int c = 0; c < 4; c++) {
                ulonglong2 t = *(const ulonglong2*)&Bs[k][c * 64 + tn0];
                bb[2 * c] = t.x; bb[2 * c + 1] = t.y;
            }
#pragma unroll
            for (int i = 0; i < 8; i++)
#pragma unroll
                for (int j = 0; j < 8; j++)
                    fma2(acc[i][j], aa[i], bb[j]);
        }
        __syncthreads();
    }

#pragma unroll
    for (int i = 0; i < 8; i++) {
        int row = bm + tm + i;
        if (row >= M) continue;
#pragma unroll
        for (int c = 0; c < 4; c++) {
            int col = bn + c * 64 + tn0;
            float4 v;
            v.x = lo2(acc[i][2 * c]);     v.y = hi2(acc[i][2 * c]);
            v.z = lo2(acc[i][2 * c + 1]); v.w = hi2(acc[i][2 * c + 1]);
            if (bias) {
                v.x += bias[col + 0]; v.y += bias[col + 1];
                v.z += bias[col + 2]; v.w += bias[col + 3];
            }
            if (act == 1) {
                v.x = tanhf(v.x); v.y = tanhf(v.y);
                v.z = tanhf(v.z); v.w = tanhf(v.w);
            }
            *(float4*)(C + (size_t)row * ldc + col) = v;
        }
    }
}

// ---------------------------------------------------------------------------
// Small-M GEMM body: M = 64 fixed, 64-wide N tile "nb", BK = 32, fp32x2 FMA.
// Requires N-tile valid, K % 32 == 0.
// ---------------------------------------------------------------------------
__device__ __forceinline__
void gemm64_body(const float* __restrict__ A, int lda,
                 const float* __restrict__ Bm, int ldb,
                 const float* __restrict__ bias,
                 float* __restrict__ C, int ldc,
                 int K, int act, int nb) {
    constexpr int BK = 32;
    __shared__ __align__(16) float As[BK][64];
    __shared__ __align__(16) float Bs[BK][64];
    const int tid = threadIdx.x;
    const int bn = nb * 64;
    const int lr = tid >> 3;          // 0..31
    const int lc = (tid & 7) << 2;    // 0..28 step 4
    const int tm = (tid >> 4) << 2;   // 0..60
    const int tn = (tid & 15) << 2;   // 0..60

    unsigned long long acc[4][2];
#pragma unroll
    for (int i = 0; i < 4; i++) { acc[i][0] = 0ull; acc[i][1] = 0ull; }

    for (int k0 = 0; k0 < K; k0 += BK) {
#pragma unroll
        for (int h = 0; h < 2; h++) {
            int r = lr + h * 32;
            float4 v = *(const float4*)(A + (size_t)r * lda + k0 + lc);
            As[lc + 0][r] = v.x; As[lc + 1][r] = v.y;
            As[lc + 2][r] = v.z; As[lc + 3][r] = v.w;
            float4 w = *(const float4*)(Bm + (size_t)(bn + r) * ldb + k0 + lc);
            Bs[lc + 0][r] = w.x; Bs[lc + 1][r] = w.y;
            Bs[lc + 2][r] = w.z; Bs[lc + 3][r] = w.w;
        }
        __syncthreads();
#pragma unroll
        for (int k = 0; k < BK; k++) {
            float4 af = *(const float4*)&As[k][tm];
            unsigned long long aa[4];
            aa[0] = pk2(af.x); aa[1] = pk2(af.y);
            aa[2] = pk2(af.z); aa[3] = pk2(af.w);
            ulonglong2 bv = *(const ulonglong2*)&Bs[k][tn];
#pragma unroll
            for (int i = 0; i < 4; i++) {
                fma2(acc[i][0], aa[i], bv.x);
                fma2(acc[i][1], aa[i], bv.y);
            }
        }
        __syncthreads();
    }
#pragma unroll
    for (int i = 0; i < 4; i++) {
        int col = bn + tn;
        float4 v;
        v.x = lo2(acc[i][0]); v.y = hi2(acc[i][0]);
        v.z = lo2(acc[i][1]); v.w = hi2(acc[i][1]);
        if (bias) {
            v.x += bias[col + 0]; v.y += bias[col + 1];
            v.z += bias[col + 2]; v.w += bias[col + 3];
        }
        if (act == 1) {
            v.x = tanhf(v.x); v.y = tanhf(v.y);
            v.z = tanhf(v.z); v.w = tanhf(v.w);
        }
        *(float4*)(C + (size_t)(tm + i) * ldc + col) = v;
    }
}

__global__ __launch_bounds__(256)
void gemm64(const float* __restrict__ A, int lda,
            const float* __restrict__ Bm, int ldb,
            const float* __restrict__ bias,
            float* __restrict__ C, int ldc, int K, int act) {
    gemm64_body(A, lda, Bm, ldb, bias, C, ldc, K, act, blockIdx.x);
}

// Encoder recurrence: both directions, K split in 2. grid (48, 2, 2)
__global__ __launch_bounds__(256)
void enc_rec_gemm(const float* __restrict__ Wh_f,
                  const float* __restrict__ Wh_b) {
    int ks = blockIdx.y, dir = blockIdx.z;
    const float* A = g_h + (size_t)dir * kB * kH + ks * 512;
    const float* B = (dir ? Wh_b : Wh_f) + ks * 512;
    float* C = g_gh + (size_t)(dir * 2 + ks) * kB * kG;
    gemm64_body(A, kH, B, kH, nullptr, C, kG, 512, 0, blockIdx.x);
}

// Decoder pre-attention GEMMs: hp (16 blocks) + ghd (48 blocks) in one launch
__global__ __launch_bounds__(256)
void dec_pre_gemm(const float* __restrict__ W_attn,
                  const float* __restrict__ Wh_d,
                  const float* __restrict__ bh_d) {
    int b = blockIdx.x;
    if (b < 16)
        gemm64_body(g_hdec, kH, W_attn, kG, nullptr, g_hp, kH, kH, 0, b);
    else
        gemm64_body(g_hdec, kH, Wh_d, kH, bh_d, g_ghd, kG, kH, 0, b - 16);
}

// Decoder w-gate GEMM: K split in 2. grid (48, 2)
__global__ __launch_bounds__(256)
void dec_gxw_gemm(const float* __restrict__ Wi_d) {
    int ks = blockIdx.y;
    gemm64_body(g_w + ks * 1024, 2 * kH,
                Wi_d + kE + ks * 1024, kXW, nullptr,
                g_gxp + (size_t)ks * kB * kG, kG, 1024, 0, blockIdx.x);
}

// ---------------------------------------------------------------------------
// GRU gate update (encoder). Partial gh sums + bh added here.
// ---------------------------------------------------------------------------
__global__ void gru_gate_enc(int s, const float* __restrict__ bh_f,
                             const float* __restrict__ bh_b) {
    int idx = blockIdx.x * blockDim.x + threadIdx.x;
    if (idx >= 2 * kB * kH) return;
    int dir = idx / (kB * kH);
    int rem = idx - dir * kB * kH;
    int b = rem / kH, j = rem - b * kH;
    int gpos = dir ? (kS - 1 - s) : s;
    const float* gx = (dir ? g_gxb : g_gxf) + ((size_t)gpos * kB + b) * kG;
    const float* g0 = g_gh + ((size_t)(dir * 2 + 0) * kB + b) * kG;
    const float* g1 = g_gh + ((size_t)(dir * 2 + 1) * kB + b) * kG;
    const float* bh = dir ? bh_b : bh_f;
    float* hvec = g_h + ((size_t)dir * kB + b) * kH;
    float h = hvec[j];
    float ghr = g0[j] + g1[j] + bh[j];
    float ghz = g0[kH + j] + g1[kH + j] + bh[kH + j];
    float ghn = g0[2 * kH + j] + g1[2 * kH + j] + bh[2 * kH + j];
    float r = 1.f / (1.f + expf(-(gx[j] + ghr)));
    float z = 1.f / (1.f + expf(-(gx[kH + j] + ghz)));
    float n = tanhf(gx[2 * kH + j] + r * ghn);
    float h2 = (1.f - z) * n + z * h;
    hvec[j] = h2;
    g_enc[((size_t)b * kS + gpos) * (2 * kH) + dir * kH + j] = h2;
}

// hcat[b][:] = [h_f[b], h_b[b]]
__global__ void hcat_kernel() {
    int idx = blockIdx.x * blockDim.x + threadIdx.x;
    if (idx >= 2 * kB * kH) return;
    int dir = idx / (kB * kH);
    int rem = idx - dir * kB * kH;
    int b = rem / kH, j = rem - b * kH;
    g_hcat[(size_t)b * 2 * kH + dir * kH + j] = g_h[idx];
}

// ---------------------------------------------------------------------------
// Fused attention: scores -> mask -> softmax -> context w.
// Writes w into g_w[b][:] and feat_t[b][H:3H].
// ---------------------------------------------------------------------------
__global__ __launch_bounds__(256)
void attn_kernel(const int* __restrict__ src,
                 const float* __restrict__ v_attn,
                 float* __restrict__ feat_t) {
    int b = blockIdx.x;
    __shared__ float sc[kS];
    int tid = threadIdx.x, warp = tid >> 5, lane = tid & 31;
    const float* hp = g_hp + (size_t)b * kH;

    for (int s = warp; s < kS; s += 8) {
        const float* ep = g_encproj + ((size_t)b * kS + s) * kH;
        float p = 0.f;
        for (int j = lane; j < kH; j += 32)
            p += v_attn[j] * tanhf(hp[j] + ep[j]);
#pragma unroll
        for (int o = 16; o; o >>= 1) p += __shfl_xor_sync(0xffffffffu, p, o);
        if (lane == 0) sc[s] = (src[s * kB + b] != kPAD) ? p : -1e10f;
    }
    __syncthreads();

    if (tid < 32) {
        float v1 = sc[tid];
        float v2 = (tid + 32 < kS) ? sc[tid + 32] : -1e30f;
        float mx = fmaxf(v1, v2);
#pragma unroll
        for (int o = 16; o; o >>= 1) mx = fmaxf(mx, __shfl_xor_sync(0xffffffffu, mx, o));
        float e1 = expf(v1 - mx);
        float e2 = (tid + 32 < kS) ? expf(v2 - mx) : 0.f;
        float sm = e1 + e2;
#pragma unroll
        for (int o = 16; o; o >>= 1) sm += __shfl_xor_sync(0xffffffffu, sm, o);
        float inv = 1.f / sm;
        sc[tid] = e1 * inv;
        if (tid + 32 < kS) sc[tid + 32] = e2 * inv;
    }
    __syncthreads();

    for (int c = tid; c < 2 * kH; c += 256) {
        float acc = 0.f;
#pragma unroll 8
        for (int s = 0; s < kS; s++)
            acc += sc[s] * g_enc[((size_t)b * kS + s) * (2 * kH) + c];
        g_w[(size_t)b * 2 * kH + c] = acc;
        feat_t[(size_t)b * kF + kH + c] = acc;
    }
}

// decoder GRU gate: gx = gxet + two partials, gh = ghd (bh folded)
__global__ void gru_gate_dec(const float* __restrict__ gxet,
                             float* __restrict__ feat_t) {
    int idx = blockIdx.x * blockDim.x + threadIdx.x;
    if (idx >= kB * kH) return;
    int b = idx / kH, j = idx - b * kH;
    size_t o = (size_t)b * kG;
    const float* gx = gxet + o;
    const float* p0 = g_gxp + o;
    const float* p1 = g_gxp + (size_t)kB * kG + o;
    const float* gh = g_ghd + o;
    float h = g_hdec[idx];
    float xr = gx[j] + p0[j] + p1[j];
    float xz = gx[kH + j] + p0[kH + j] + p1[kH + j];
    float xn = gx[2 * kH + j] + p0[2 * kH + j] + p1[2 * kH + j];
    float r = 1.f / (1.f + expf(-(xr + gh[j])));
    float z = 1.f / (1.f + expf(-(xz + gh[kH + j])));
    float n = tanhf(xn + r * gh[2 * kH + j]);
    float h2 = (1.f - z) * n + z * h;
    g_hdec[idx] = h2;
    feat_t[(size_t)b * kF + j] = h2;
}

// ---------------------------------------------------------------------------
// Host orchestration (graph-capturable: kernel launches only)
// ---------------------------------------------------------------------------
extern "C" void kernel_launch(void* const* d_in, const int* in_sizes, int n_in,
                              void* d_out, int out_size) {
    const int*   src     = (const int*)d_in[0];
    const int*   trg     = (const int*)d_in[1];
    const float* emb_enc = (const float*)d_in[2];
    const float* Wi_f    = (const float*)d_in[3];
    const float* Wh_f    = (const float*)d_in[4];
    const float* bi_f    = (const float*)d_in[5];
    const float* bh_f    = (const float*)d_in[6];
    const float* Wi_b    = (const float*)d_in[7];
    const float* Wh_b    = (const float*)d_in[8];
    const float* bi_b    = (const float*)d_in[9];
    const float* bh_b    = (const float*)d_in[10];
    const float* W_fc    = (const float*)d_in[11];
    const float* b_fc    = (const float*)d_in[12];
    const float* W_attn  = (const float*)d_in[13];
    const float* b_attn  = (const float*)d_in[14];
    const float* v_attn  = (const float*)d_in[15];
    const float* emb_dec = (const float*)d_in[16];
    const float* Wi_d    = (const float*)d_in[17];
    const float* Wh_d    = (const float*)d_in[18];
    const float* bi_d    = (const float*)d_in[19];
    const float* bh_d    = (const float*)d_in[20];
    const float* W_out   = (const float*)d_in[21];
    const float* b_out   = (const float*)d_in[22];
    float* out = (float*)d_out;

    float *p_emb, *p_gxf, *p_gxb, *p_enc, *p_ep, *p_hcat,
          *p_hdec, *p_gxet, *p_feat;
    cudaGetSymbolAddress((void**)&p_emb, g_emb);
    cudaGetSymbolAddress((void**)&p_gxf, g_gxf);
    cudaGetSymbolAddress((void**)&p_gxb, g_gxb);
    cudaGetSymbolAddress((void**)&p_enc, g_enc);
    cudaGetSymbolAddress((void**)&p_ep, g_encproj);
    cudaGetSymbolAddress((void**)&p_hcat, g_hcat);
    cudaGetSymbolAddress((void**)&p_hdec, g_hdec);
    cudaGetSymbolAddress((void**)&p_gxet, g_gxet);
    cudaGetSymbolAddress((void**)&p_feat, g_feat);

    // 0. zero output timestep 0 + encoder hidden
    init_kernel<<<((size_t)kB * kV + 255) / 256, 256>>>(out);

    // 1. embedding gathers (encoder all, decoder all steps)
    enc_embed_kernel<<<kS * kB, 128>>>(src, emb_enc);
    dec_embed_all<<<(kT - 1) * kB, 128>>>(trg, emb_dec);

    // 2. batched input-gate GEMMs
    {
        dim3 g(kG / 256, (kS * kB) / 128);
        sgemm_tn256<<<g, 256>>>(p_emb, kE, Wi_f, kE, bi_f, p_gxf, kG,
                                kS * kB, kG, kE, 0);
        sgemm_tn256<<<g, 256>>>(p_emb, kE, Wi_b, kE, bi_b, p_gxb, kG,
                                kS * kB, kG, kE, 0);
        // decoder et-part of input gates, all steps, bias folded
        dim3 g2(kG / 256, ((kT - 1) * kB + 127) / 128);
        sgemm_tn256<<<g2, 256>>>(p_feat + 3 * kH, kF, Wi_d, kXW, bi_d,
                                 p_gxet, kG, (kT - 1) * kB, kG, kE, 0);
    }

    // 3. encoder recurrence (fwd+bwd, K-split 2)
    for (int s = 0; s < kS; s++) {
        dim3 gd(kG / 64, 2, 2);
        enc_rec_gemm<<<gd, 256>>>(Wh_f, Wh_b);
        gru_gate_enc<<<(2 * kB * kH) / 256, 256>>>(s, bh_f, bh_b);
    }

    // 4. decoder init hidden = tanh([hf,hb] @ W_fc^T + b_fc)
    hcat_kernel<<<(2 * kB * kH) / 256, 256>>>();
    gemm64<<<kH / 64, 256>>>(p_hcat, 2 * kH, W_fc, 2 * kH, b_fc,
                             p_hdec, kH, 2 * kH, 1);

    // 5. precompute encoder attention projection (b_attn folded in)
    {
        dim3 g(kH / 256, (kB * kS) / 128);
        sgemm_tn256<<<g, 256>>>(p_enc, 2 * kH, W_attn + kH, kG, b_attn,
                                p_ep, kH, kB * kS, kH, 2 * kH, 0);
    }

    // 6. decoder loop (4 launches per step)
    for (int t = 0; t < kT - 1; t++) {
        float* feat_t = p_feat + (size_t)t * kB * kF;
        dec_pre_gemm<<<64, 256>>>(W_attn, Wh_d, bh_d);
        attn_kernel<<<kB, 256>>>(src, v_attn, feat_t);
        dec_gxw_gemm<<<dim3(kG / 64, 2), 256>>>(Wi_d);
        gru_gate_dec<<<(kB * kH) / 256, 256>>>(p_gxet + (size_t)t * kB * kG,
                                               feat_t);
    }

    // 7. batched output projection for all timesteps at once
    {
        int M = (kT - 1) * kB; // 1984
        dim3 g(kV / 256, (M + 127) / 128);
        sgemm_tn256<<<g, 256>>>(p_feat, kF, W_out, kF, b_out,
                                out + (size_t)kB * kV, kV, M, kV, kF, 0);
    }
}

// round 5
// speedup vs baseline: 3.2996x; 1.5808x over previous
#include <cuda_runtime.h>
#include <cuda_bf16.h>
#include <math.h>
#include <stdint.h>

// ---------------------------------------------------------------------------
// Problem constants
// ---------------------------------------------------------------------------
namespace {
constexpr int kS = 48;          // source length
constexpr int kT = 32;          // target length
constexpr int kB = 64;          // batch
constexpr int kH = 1024;        // hidden
constexpr int kE = 512;         // embed
constexpr int kV = 32000;       // vocab
constexpr int kG = 3 * kH;      // 3072 gates
constexpr int kF = 3 * kH + kE; // 3584 out-proj features
constexpr int kXW = kE + 2*kH;  // 2560 decoder GRU input width
constexpr int kPAD = 1;
constexpr int kMR = (kT - 1) * kB; // 1984 output rows
constexpr int kMP = 2048;          // padded rows for tensor GEMM
}

// ---------------------------------------------------------------------------
// Packed fp32x2 helpers (FFMA2)
// ---------------------------------------------------------------------------
__device__ __forceinline__ unsigned long long pk2(float x) {
    unsigned long long r;
    unsigned u = __float_as_uint(x);
    asm("mov.b64 %0, {%1, %1};" : "=l"(r) : "r"(u));
    return r;
}
__device__ __forceinline__ void fma2(unsigned long long& d,
                                     unsigned long long a,
                                     unsigned long long b) {
    asm("fma.rn.f32x2 %0, %1, %2, %0;" : "+l"(d) : "l"(a), "l"(b));
}
__device__ __forceinline__ float lo2(unsigned long long v) {
    return __uint_as_float((unsigned)v);
}
__device__ __forceinline__ float hi2(unsigned long long v) {
    return __uint_as_float((unsigned)(v >> 32));
}

// ---------------------------------------------------------------------------
// Plain-PTX helpers: cp.async / ldmatrix / mma.sync (NO arch-specific ops)
// ---------------------------------------------------------------------------
__device__ __forceinline__ uint32_t smem_u32(const void* p) {
    uint32_t a;
    asm("{ .reg .u64 t; cvta.to.shared.u64 t, %1; cvt.u32.u64 %0, t; }"
        : "=r"(a) : "l"(p));
    return a;
}
#define CP_ASYNC16(dst, src) \
    asm volatile("cp.async.cg.shared.global [%0], [%1], 16;" \
                 :: "r"(dst), "l"(src) : "memory")
#define CP_COMMIT() asm volatile("cp.async.commit_group;" ::: "memory")
#define CP_WAIT1()  asm volatile("cp.async.wait_group 1;" ::: "memory")
#define CP_WAIT0()  asm volatile("cp.async.wait_group 0;" ::: "memory")

__device__ __forceinline__ void ldsm4(uint32_t* r, uint32_t addr) {
    asm volatile("ldmatrix.sync.aligned.m8n8.x4.shared.b16 {%0,%1,%2,%3}, [%4];"
                 : "=r"(r[0]), "=r"(r[1]), "=r"(r[2]), "=r"(r[3])
                 : "r"(addr));
}
__device__ __forceinline__ void mma16816(float* d, const uint32_t* a,
                                         const uint32_t* b) {
    asm volatile(
        "mma.sync.aligned.m16n8k16.row.col.f32.bf16.bf16.f32 "
        "{%0,%1,%2,%3}, {%4,%5,%6,%7}, {%8,%9}, {%0,%1,%2,%3};"
        : "+f"(d[0]), "+f"(d[1]), "+f"(d[2]), "+f"(d[3])
        : "r"(a[0]), "r"(a[1]), "r"(a[2]), "r"(a[3]),
          "r"(b[0]), "r"(b[1]));
}

// ---------------------------------------------------------------------------
// Persistent scratch
// ---------------------------------------------------------------------------
__device__ float g_emb[(size_t)kS * kB * kE];
__device__ float g_gxf[(size_t)kS * kB * kG];
__device__ float g_gxb[(size_t)kS * kB * kG];
__device__ float g_enc[(size_t)kB * kS * 2 * kH];
__device__ float g_encproj[(size_t)kB * kS * kH];
__device__ float g_h[2 * kB * kH];
__device__ float g_gh[4 * kB * kG];
__device__ float g_hcat[kB * 2 * kH];
__device__ float g_hdec[kB * kH];
__device__ float g_hp[kB * kH];
__device__ float g_w[kB * 2 * kH];
__device__ float g_gxp[2 * kB * kG];
__device__ float g_ghd[kB * kG];
__device__ float g_gxet[(size_t)kMR * kG];
__device__ float g_feat[(size_t)kMR * kF];         // [h2, w, et] per step
// bf16 split operands for the tensor-core output GEMM
__device__ __nv_bfloat16 g_Ahi[(size_t)kMP * kF];
__device__ __nv_bfloat16 g_Alo[(size_t)kMP * kF];
__device__ __nv_bfloat16 g_Bhi[(size_t)kV * kF];
__device__ __nv_bfloat16 g_Blo[(size_t)kV * kF];

// ---------------------------------------------------------------------------
__global__ void init_kernel(float* __restrict__ out0) {
    size_t i = (size_t)blockIdx.x * blockDim.x + threadIdx.x;
    if (i < (size_t)kB * kV) out0[i] = 0.f;
    if (i < (size_t)2 * kB * kH) g_h[i] = 0.f;
}

__global__ void enc_embed_kernel(const int* __restrict__ src,
                                 const float* __restrict__ table) {
    int row = blockIdx.x;
    int tok = src[row];
    const float4* sp = (const float4*)(table + (size_t)tok * kE);
    float4* dp = (float4*)(g_emb + (size_t)row * kE);
    dp[threadIdx.x] = sp[threadIdx.x];
}

__global__ void dec_embed_all(const int* __restrict__ trg,
                              const float* __restrict__ emb_dec) {
    int row = blockIdx.x;
    int tok = trg[row];
    float4 v = ((const float4*)(emb_dec + (size_t)tok * kE))[threadIdx.x];
    ((float4*)(g_feat + (size_t)row * kF + 3 * kH))[threadIdx.x] = v;
}

// ---------------------------------------------------------------------------
// bf16 split conversion kernels
// ---------------------------------------------------------------------------
__global__ void cvt_split(const float* __restrict__ src,
                          __nv_bfloat16* __restrict__ hi,
                          __nv_bfloat16* __restrict__ lo, size_t n) {
    size_t i = (size_t)blockIdx.x * blockDim.x + threadIdx.x;
    if (i >= n) return;
    float v = src[i];
    __nv_bfloat16 h = __float2bfloat16(v);
    hi[i] = h;
    lo[i] = __float2bfloat16(v - __bfloat162float(h));
}

__global__ void cvt_feat_split() {
    size_t i = (size_t)blockIdx.x * blockDim.x + threadIdx.x;
    if (i >= (size_t)kMP * kF) return;
    size_t row = i / kF;
    float v = (row < (size_t)kMR) ? g_feat[i] : 0.f;
    __nv_bfloat16 h = __float2bfloat16(v);
    g_Ahi[i] = h;
    g_Alo[i] = __float2bfloat16(v - __bfloat162float(h));
}

// ---------------------------------------------------------------------------
// HMMA output projection: out[M=1984, N=32000] =
//   (Ahi+Alo)(Bhi+Blo)^T + bias   (bf16x3 split, fp32 accumulate)
// Tile 128x128, K-slab 64 (128B rows, SW128 swizzle), 8 warps (4x2),
// warp tile 32x64 (2x8 m16n8k16 atoms), 2-stage cp.async double buffer.
// Grid: (16 m-tiles, 250 n-tiles), 256 threads.
// ---------------------------------------------------------------------------
namespace outg {
constexpr int BM = 128, BN = 128, BK = 64;
constexpr int NSLAB = kF / BK;              // 56
constexpr int HALF = 16384;                 // one operand-half tile bytes
constexpr int STAGE = 4 * HALF;             // Ahi|Alo|Bhi|Blo = 65536
constexpr int SMEM_SZ = 2 * STAGE;          // 131072
}

__device__ __forceinline__ void outg_prefetch(int slab, uint32_t buf,
                                              int tid, int m0, int n0) {
    using namespace outg;
    const int k0 = slab * BK;
#pragma unroll
    for (int i = 0; i < 4; i++) {
        int id = tid + i * 256;             // 0..1023
        int row = id >> 3, c = id & 7;
        uint32_t off = (uint32_t)(row << 7) + (c << 4);
        uint32_t sw = off ^ ((off >> 3) & 0x70);
        size_t ga = (size_t)(m0 + row) * kF + k0 + c * 8;
        size_t gb = (size_t)(n0 + row) * kF + k0 + c * 8;
        CP_ASYNC16(buf + sw, g_Ahi + ga);
        CP_ASYNC16(buf + HALF + sw, g_Alo + ga);
        CP_ASYNC16(buf + 2 * HALF + sw, g_Bhi + gb);
        CP_ASYNC16(buf + 3 * HALF + sw, g_Blo + gb);
    }
}

__device__ __forceinline__ void outg_compute(uint32_t buf, int lane,
                                             int wm, int wn,
                                             float acc[2][8][4]) {
    using namespace outg;
    const int g = lane >> 3, r = lane & 7;
#pragma unroll
    for (int ks = 0; ks < 4; ks++) {
        uint32_t ahi[2][4], alo[2][4];
#pragma unroll
        for (int mi = 0; mi < 2; mi++) {
            int row = wm + mi * 16 + ((g & 1) << 3) + r;
            int chunk = ks * 2 + (g >> 1);
            uint32_t off = (uint32_t)(row << 7) + (chunk << 4);
            uint32_t sw = off ^ ((off >> 3) & 0x70);
            ldsm4(ahi[mi], buf + sw);
            ldsm4(alo[mi], buf + HALF + sw);
        }
        uint32_t bhi[4][4], blo[4][4];
#pragma unroll
        for (int np = 0; np < 4; np++) {
            int row = wn + np * 16 + ((g >> 1) << 3) + r;
            int chunk = ks * 2 + (g & 1);
            uint32_t off = (uint32_t)(row << 7) + (chunk << 4);
            uint32_t sw = off ^ ((off >> 3) & 0x70);
            ldsm4(bhi[np], buf + 2 * HALF + sw);
            ldsm4(blo[np], buf + 3 * HALF + sw);
        }
#pragma unroll
        for (int mi = 0; mi < 2; mi++) {
#pragma unroll
            for (int np = 0; np < 4; np++) {
#pragma unroll
                for (int a = 0; a < 2; a++) {
                    uint32_t bh[2] = { bhi[np][2 * a], bhi[np][2 * a + 1] };
                    uint32_t bl[2] = { blo[np][2 * a], blo[np][2 * a + 1] };
                    float* d = acc[mi][np * 2 + a];
                    mma16816(d, ahi[mi], bh);   // hi * hi
                    mma16816(d, ahi[mi], bl);   // hi * lo
                    mma16816(d, alo[mi], bh);   // lo * hi
                }
            }
        }
    }
}

__global__ __launch_bounds__(256, 1)
void outgemm_kernel(const float* __restrict__ bias, float* __restrict__ out) {
    using namespace outg;
    extern __shared__ char smem[];
    const uint32_t sb = smem_u32(smem);
    const int tid = threadIdx.x;
    const int wid = tid >> 5, lane = tid & 31;
    const int m0 = blockIdx.x * BM;
    const int n0 = blockIdx.y * BN;
    const int wm = (wid & 3) * 32;   // warp m offset in tile
    const int wn = (wid >> 2) * 64;  // warp n offset in tile

    float acc[2][8][4];
#pragma unroll
    for (int i = 0; i < 2; i++)
#pragma unroll
        for (int j = 0; j < 8; j++)
#pragma unroll
            for (int q = 0; q < 4; q++) acc[i][j][q] = 0.f;

    outg_prefetch(0, sb, tid, m0, n0);
    CP_COMMIT();
    outg_prefetch(1, sb + STAGE, tid, m0, n0);
    CP_COMMIT();

    for (int s = 0; s < NSLAB; s++) {
        const int st = s & 1;
        if (s == NSLAB - 1) { CP_WAIT0(); } else { CP_WAIT1(); }
        __syncthreads();
        outg_compute(sb + st * STAGE, lane, wm, wn, acc);
        __syncthreads();
        if (s + 2 < NSLAB) {
            outg_prefetch(s + 2, sb + st * STAGE, tid, m0, n0);
            CP_COMMIT();
        }
    }

    // epilogue: register accumulators -> gmem with bias
    const int r0 = m0 + wm + (lane >> 2);
    const int c0 = n0 + wn + (lane & 3) * 2;
#pragma unroll
    for (int mi = 0; mi < 2; mi++) {
#pragma unroll
        for (int ni = 0; ni < 8; ni++) {
            int row = r0 + mi * 16;
            int col = c0 + ni * 8;
            const float* d = acc[mi][ni];
            float b0 = bias[col], b1 = bias[col + 1];
            if (row < kMR) {
                out[(size_t)row * kV + col]     = d[0] + b0;
                out[(size_t)row * kV + col + 1] = d[1] + b1;
            }
            if (row + 8 < kMR) {
                out[(size_t)(row + 8) * kV + col]     = d[2] + b0;
                out[(size_t)(row + 8) * kV + col + 1] = d[3] + b1;
            }
        }
    }
}

// ---------------------------------------------------------------------------
// SIMT GEMMs (FFMA2) for the rest of the network
// ---------------------------------------------------------------------------
__global__ __launch_bounds__(256, 1)
void sgemm_tn256(const float* __restrict__ A, int lda,
                 const float* __restrict__ Bm, int ldb,
                 const float* __restrict__ bias,
                 float* __restrict__ C, int ldc,
                 int M, int N, int K, int act) {
    constexpr int BM = 128, BN = 256, BK = 16;
    __shared__ __align__(16) float As[BK][BM];
    __shared__ __align__(16) float Bs[BK][BN];
    const int tid = threadIdx.x;
    const int bm = blockIdx.y * BM;
    const int bn = blockIdx.x * BN;
    const int lr = tid >> 2;
    const int lc = (tid & 3) << 2;
    const int tm = (tid >> 4) << 3;
    const int tn0 = (tid & 15) << 2;

    unsigned long long acc[8][8];
#pragma unroll
    for (int i = 0; i < 8; i++)
#pragma unroll
        for (int j = 0; j < 8; j++) acc[i][j] = 0ull;

    float4 ra[2], rb[4];
    {
#pragma unroll
        for (int h = 0; h < 2; h++) {
            int gr = bm + lr + h * 64;
            ra[h] = (gr < M) ? *(const float4*)(A + (size_t)gr * lda + lc)
                             : make_float4(0.f, 0.f, 0.f, 0.f);
        }
#pragma unroll
        for (int h = 0; h < 4; h++) {
            int gc = bn + lr + h * 64;
            rb[h] = *(const float4*)(Bm + (size_t)gc * ldb + lc);
        }
    }

    for (int k0 = 0; k0 < K; k0 += BK) {
#pragma unroll
        for (int h = 0; h < 2; h++) {
            int r = lr + h * 64;
            As[lc + 0][r] = ra[h].x; As[lc + 1][r] = ra[h].y;
            As[lc + 2][r] = ra[h].z; As[lc + 3][r] = ra[h].w;
        }
#pragma unroll
        for (int h = 0; h < 4; h++) {
            int r = lr + h * 64;
            Bs[lc + 0][r] = rb[h].x; Bs[lc + 1][r] = rb[h].y;
            Bs[lc + 2][r] = rb[h].z; Bs[lc + 3][r] = rb[h].w;
        }
        __syncthreads();

        if (k0 + BK < K) {
            int kn = k0 + BK;
#pragma unroll
            for (int h = 0; h < 2; h++) {
                int gr = bm + lr + h * 64;
                ra[h] = (gr < M) ? *(const float4*)(A + (size_t)gr * lda + kn + lc)
                                 : make_float4(0.f, 0.f, 0.f, 0.f);
            }
#pragma unroll
            for (int h = 0; h < 4; h++) {
                int gc = bn + lr + h * 64;
                rb[h] = *(const float4*)(Bm + (size_t)gc * ldb + kn + lc);
            }
        }

#pragma unroll
        for (int k = 0; k < BK; k++) {
            float4 a0 = *(const float4*)&As[k][tm];
            float4 a1 = *(const float4*)&As[k][tm + 4];
            unsigned long long aa[8];
            aa[0] = pk2(a0.x); aa[1] = pk2(a0.y);
            aa[2] = pk2(a0.z); aa[3] = pk2(a0.w);
            aa[4] = pk2(a1.x); aa[5] = pk2(a1.y);
            aa[6] = pk2(a1.z); aa[7] = pk2(a1.w);
            unsigned long long bb[8];
#pragma unroll
            for (int c = 0; c < 4; c++) {
                ulonglong2 t = *(const ulonglong2*)&Bs[k][c * 64 + tn0];
                bb[2 * c] = t.x; bb[2 * c + 1] = t.y;
            }
#pragma unroll
            for (int i = 0; i < 8; i++)
#pragma unroll
                for (int j = 0; j < 8; j++)
                    fma2(acc[i][j], aa[i], bb[j]);
        }
        __syncthreads();
    }

#pragma unroll
    for (int i = 0; i < 8; i++) {
        int row = bm + tm + i;
        if (row >= M) continue;
#pragma unroll
        for (int c = 0; c < 4; c++) {
            int col = bn + c * 64 + tn0;
            float4 v;
            v.x = lo2(acc[i][2 * c]);     v.y = hi2(acc[i][2 * c]);
            v.z = lo2(acc[i][2 * c + 1]); v.w = hi2(acc[i][2 * c + 1]);
            if (bias) {
                v.x += bias[col + 0]; v.y += bias[col + 1];
                v.z += bias[col + 2]; v.w += bias[col + 3];
            }
            if (act == 1) {
                v.x = tanhf(v.x); v.y = tanhf(v.y);
                v.z = tanhf(v.z); v.w = tanhf(v.w);
            }
            *(float4*)(C + (size_t)row * ldc + col) = v;
        }
    }
}

__device__ __forceinline__
void gemm64_body(const float* __restrict__ A, int lda,
                 const float* __restrict__ Bm, int ldb,
                 const float* __restrict__ bias,
                 float* __restrict__ C, int ldc,
                 int K, int act, int nb) {
    constexpr int BK = 32;
    __shared__ __align__(16) float As[BK][64];
    __shared__ __align__(16) float Bs[BK][64];
    const int tid = threadIdx.x;
    const int bn = nb * 64;
    const int lr = tid >> 3;
    const int lc = (tid & 7) << 2;
    const int tm = (tid >> 4) << 2;
    const int tn = (tid & 15) << 2;

    unsigned long long acc[4][2];
#pragma unroll
    for (int i = 0; i < 4; i++) { acc[i][0] = 0ull; acc[i][1] = 0ull; }

    for (int k0 = 0; k0 < K; k0 += BK) {
#pragma unroll
        for (int h = 0; h < 2; h++) {
            int r = lr + h * 32;
            float4 v = *(const float4*)(A + (size_t)r * lda + k0 + lc);
            As[lc + 0][r] = v.x; As[lc + 1][r] = v.y;
            As[lc + 2][r] = v.z; As[lc + 3][r] = v.w;
            float4 w = *(const float4*)(Bm + (size_t)(bn + r) * ldb + k0 + lc);
            Bs[lc + 0][r] = w.x; Bs[lc + 1][r] = w.y;
            Bs[lc + 2][r] = w.z; Bs[lc + 3][r] = w.w;
        }
        __syncthreads();
#pragma unroll
        for (int k = 0; k < BK; k++) {
            float4 af = *(const float4*)&As[k][tm];
            unsigned long long aa[4];
            aa[0] = pk2(af.x); aa[1] = pk2(af.y);
            aa[2] = pk2(af.z); aa[3] = pk2(af.w);
            ulonglong2 bv = *(const ulonglong2*)&Bs[k][tn];
#pragma unroll
            for (int i = 0; i < 4; i++) {
                fma2(acc[i][0], aa[i], bv.x);
                fma2(acc[i][1], aa[i], bv.y);
            }
        }
        __syncthreads();
    }
#pragma unroll
    for (int i = 0; i < 4; i++) {
        int col = bn + tn;
        float4 v;
        v.x = lo2(acc[i][0]); v.y = hi2(acc[i][0]);
        v.z = lo2(acc[i][1]); v.w = hi2(acc[i][1]);
        if (bias) {
            v.x += bias[col + 0]; v.y += bias[col + 1];
            v.z += bias[col + 2]; v.w += bias[col + 3];
        }
        if (act == 1) {
            v.x = tanhf(v.x); v.y = tanhf(v.y);
            v.z = tanhf(v.z); v.w = tanhf(v.w);
        }
        *(float4*)(C + (size_t)(tm + i) * ldc + col) = v;
    }
}

__global__ __launch_bounds__(256)
void gemm64(const float* __restrict__ A, int lda,
            const float* __restrict__ Bm, int ldb,
            const float* __restrict__ bias,
            float* __restrict__ C, int ldc, int K, int act) {
    gemm64_body(A, lda, Bm, ldb, bias, C, ldc, K, act, blockIdx.x);
}

__global__ __launch_bounds__(256)
void enc_rec_gemm(const float* __restrict__ Wh_f,
                  const float* __restrict__ Wh_b) {
    int ks = blockIdx.y, dir = blockIdx.z;
    const float* A = g_h + (size_t)dir * kB * kH + ks * 512;
    const float* B = (dir ? Wh_b : Wh_f) + ks * 512;
    float* C = g_gh + (size_t)(dir * 2 + ks) * kB * kG;
    gemm64_body(A, kH, B, kH, nullptr, C, kG, 512, 0, blockIdx.x);
}

__global__ __launch_bounds__(256)
void dec_pre_gemm(const float* __restrict__ W_attn,
                  const float* __restrict__ Wh_d,
                  const float* __restrict__ bh_d) {
    int b = blockIdx.x;
    if (b < 16)
        gemm64_body(g_hdec, kH, W_attn, kG, nullptr, g_hp, kH, kH, 0, b);
    else
        gemm64_body(g_hdec, kH, Wh_d, kH, bh_d, g_ghd, kG, kH, 0, b - 16);
}

__global__ __launch_bounds__(256)
void dec_gxw_gemm(const float* __restrict__ Wi_d) {
    int ks = blockIdx.y;
    gemm64_body(g_w + ks * 1024, 2 * kH,
                Wi_d + kE + ks * 1024, kXW, nullptr,
                g_gxp + (size_t)ks * kB * kG, kG, 1024, 0, blockIdx.x);
}

// ---------------------------------------------------------------------------
__global__ void gru_gate_enc(int s, const float* __restrict__ bh_f,
                             const float* __restrict__ bh_b) {
    int idx = blockIdx.x * blockDim.x + threadIdx.x;
    if (idx >= 2 * kB * kH) return;
    int dir = idx / (kB * kH);
    int rem = idx - dir * (kB * kH);
    int b = rem / kH, j = rem - b * kH;
    int gpos = dir ? (kS - 1 - s) : s;
    const float* gx = (dir ? g_gxb : g_gxf) + ((size_t)gpos * kB + b) * kG;
    const float* g0 = g_gh + ((size_t)(dir * 2 + 0) * kB + b) * kG;
    const float* g1 = g_gh + ((size_t)(dir * 2 + 1) * kB + b) * kG;
    const float* bh = dir ? bh_b : bh_f;
    float* hvec = g_h + ((size_t)dir * kB + b) * kH;
    float h = hvec[j];
    float ghr = g0[j] + g1[j] + bh[j];
    float ghz = g0[kH + j] + g1[kH + j] + bh[kH + j];
    float ghn = g0[2 * kH + j] + g1[2 * kH + j] + bh[2 * kH + j];
    float r = 1.f / (1.f + expf(-(gx[j] + ghr)));
    float z = 1.f / (1.f + expf(-(gx[kH + j] + ghz)));
    float n = tanhf(gx[2 * kH + j] + r * ghn);
    float h2 = (1.f - z) * n + z * h;
    hvec[j] = h2;
    g_enc[((size_t)b * kS + gpos) * (2 * kH) + dir * kH + j] = h2;
}

__global__ void hcat_kernel() {
    int idx = blockIdx.x * blockDim.x + threadIdx.x;
    if (idx >= 2 * kB * kH) return;
    int dir = idx / (kB * kH);
    int rem = idx - dir * (kB * kH);
    int b = rem / kH, j = rem - b * kH;
    g_hcat[(size_t)b * 2 * kH + dir * kH + j] = g_h[idx];
}

__global__ __launch_bounds__(256)
void attn_kernel(const int* __restrict__ src,
                 const float* __restrict__ v_attn,
                 float* __restrict__ feat_t) {
    int b = blockIdx.x;
    __shared__ float sc[kS];
    int tid = threadIdx.x, warp = tid >> 5, lane = tid & 31;
    const float* hp = g_hp + (size_t)b * kH;

    for (int s = warp; s < kS; s += 8) {
        const float* ep = g_encproj + ((size_t)b * kS + s) * kH;
        float p = 0.f;
        for (int j = lane; j < kH; j += 32)
            p += v_attn[j] * tanhf(hp[j] + ep[j]);
#pragma unroll
        for (int o = 16; o; o >>= 1) p += __shfl_xor_sync(0xffffffffu, p, o);
        if (lane == 0) sc[s] = (src[s * kB + b] != kPAD) ? p : -1e10f;
    }
    __syncthreads();

    if (tid < 32) {
        float v1 = sc[tid];
        float v2 = (tid + 32 < kS) ? sc[tid + 32] : -1e30f;
        float mx = fmaxf(v1, v2);
#pragma unroll
        for (int o = 16; o; o >>= 1) mx = fmaxf(mx, __shfl_xor_sync(0xffffffffu, mx, o));
        float e1 = expf(v1 - mx);
        float e2 = (tid + 32 < kS) ? expf(v2 - mx) : 0.f;
        float sm = e1 + e2;
#pragma unroll
        for (int o = 16; o; o >>= 1) sm += __shfl_xor_sync(0xffffffffu, sm, o);
        float inv = 1.f / sm;
        sc[tid] = e1 * inv;
        if (tid + 32 < kS) sc[tid + 32] = e2 * inv;
    }
    __syncthreads();

    for (int c = tid; c < 2 * kH; c += 256) {
        float acc = 0.f;
#pragma unroll 8
        for (int s = 0; s < kS; s++)
            acc += sc[s] * g_enc[((size_t)b * kS + s) * (2 * kH) + c];
        g_w[(size_t)b * 2 * kH + c] = acc;
        feat_t[(size_t)b * kF + kH + c] = acc;
    }
}

__global__ void gru_gate_dec(const float* __restrict__ gxet,
                             float* __restrict__ feat_t) {
    int idx = blockIdx.x * blockDim.x + threadIdx.x;
    if (idx >= kB * kH) return;
    int b = idx / kH, j = idx - b * kH;
    size_t o = (size_t)b * kG;
    const float* gx = gxet + o;
    const float* p0 = g_gxp + o;
    const float* p1 = g_gxp + (size_t)kB * kG + o;
    const float* gh = g_ghd + o;
    float h = g_hdec[idx];
    float xr = gx[j] + p0[j] + p1[j];
    float xz = gx[kH + j] + p0[kH + j] + p1[kH + j];
    float xn = gx[2 * kH + j] + p0[2 * kH + j] + p1[2 * kH + j];
    float r = 1.f / (1.f + expf(-(xr + gh[j])));
    float z = 1.f / (1.f + expf(-(xz + gh[kH + j])));
    float n = tanhf(xn + r * gh[2 * kH + j]);
    float h2 = (1.f - z) * n + z * h;
    g_hdec[idx] = h2;
    feat_t[(size_t)b * kF + j] = h2;
}

// ---------------------------------------------------------------------------
// Host orchestration
// ---------------------------------------------------------------------------
extern "C" void kernel_launch(void* const* d_in, const int* in_sizes, int n_in,
                              void* d_out, int out_size) {
    const int*   src     = (const int*)d_in[0];
    const int*   trg     = (const int*)d_in[1];
    const float* emb_enc = (const float*)d_in[2];
    const float* Wi_f    = (const float*)d_in[3];
    const float* Wh_f    = (const float*)d_in[4];
    const float* bi_f    = (const float*)d_in[5];
    const float* bh_f    = (const float*)d_in[6];
    const float* Wi_b    = (const float*)d_in[7];
    const float* Wh_b    = (const float*)d_in[8];
    const float* bi_b    = (const float*)d_in[9];
    const float* bh_b    = (const float*)d_in[10];
    const float* W_fc    = (const float*)d_in[11];
    const float* b_fc    = (const float*)d_in[12];
    const float* W_attn  = (const float*)d_in[13];
    const float* b_attn  = (const float*)d_in[14];
    const float* v_attn  = (const float*)d_in[15];
    const float* emb_dec = (const float*)d_in[16];
    const float* Wi_d    = (const float*)d_in[17];
    const float* Wh_d    = (const float*)d_in[18];
    const float* bi_d    = (const float*)d_in[19];
    const float* bh_d    = (const float*)d_in[20];
    const float* W_out   = (const float*)d_in[21];
    const float* b_out   = (const float*)d_in[22];
    float* out = (float*)d_out;

    float *p_emb, *p_gxf, *p_gxb, *p_enc, *p_ep, *p_hcat,
          *p_hdec, *p_gxet, *p_feat;
    __nv_bfloat16 *p_Bhi, *p_Blo;
    cudaGetSymbolAddress((void**)&p_emb, g_emb);
    cudaGetSymbolAddress((void**)&p_gxf, g_gxf);
    cudaGetSymbolAddress((void**)&p_gxb, g_gxb);
    cudaGetSymbolAddress((void**)&p_enc, g_enc);
    cudaGetSymbolAddress((void**)&p_ep, g_encproj);
    cudaGetSymbolAddress((void**)&p_hcat, g_hcat);
    cudaGetSymbolAddress((void**)&p_hdec, g_hdec);
    cudaGetSymbolAddress((void**)&p_gxet, g_gxet);
    cudaGetSymbolAddress((void**)&p_feat, g_feat);
    cudaGetSymbolAddress((void**)&p_Bhi, g_Bhi);
    cudaGetSymbolAddress((void**)&p_Blo, g_Blo);

    cudaFuncSetAttribute(outgemm_kernel,
                         cudaFuncAttributeMaxDynamicSharedMemorySize,
                         outg::SMEM_SZ);

    // 0. zero output timestep 0 + encoder hidden
    init_kernel<<<((size_t)kB * kV + 255) / 256, 256>>>(out);

    // 0b. split-convert W_out to bf16 hi/lo
    {
        size_t n = (size_t)kV * kF;
        cvt_split<<<(unsigned)((n + 255) / 256), 256>>>(W_out, p_Bhi, p_Blo, n);
    }

    // 1. embedding gathers
    enc_embed_kernel<<<kS * kB, 128>>>(src, emb_enc);
    dec_embed_all<<<kMR, 128>>>(trg, emb_dec);

    // 2. batched input-gate GEMMs
    {
        dim3 g(kG / 256, (kS * kB) / 128);
        sgemm_tn256<<<g, 256>>>(p_emb, kE, Wi_f, kE, bi_f, p_gxf, kG,
                                kS * kB, kG, kE, 0);
        sgemm_tn256<<<g, 256>>>(p_emb, kE, Wi_b, kE, bi_b, p_gxb, kG,
                                kS * kB, kG, kE, 0);
        dim3 g2(kG / 256, (kMR + 127) / 128);
        sgemm_tn256<<<g2, 256>>>(p_feat + 3 * kH, kF, Wi_d, kXW, bi_d,
                                 p_gxet, kG, kMR, kG, kE, 0);
    }

    // 3. encoder recurrence
    for (int s = 0; s < kS; s++) {
        dim3 gd(kG / 64, 2, 2);
        enc_rec_gemm<<<gd, 256>>>(Wh_f, Wh_b);
        gru_gate_enc<<<(2 * kB * kH) / 256, 256>>>(s, bh_f, bh_b);
    }

    // 4. decoder init hidden
    hcat_kernel<<<(2 * kB * kH) / 256, 256>>>();
    gemm64<<<kH / 64, 256>>>(p_hcat, 2 * kH, W_fc, 2 * kH, b_fc,
                             p_hdec, kH, 2 * kH, 1);

    // 5. encoder attention projection
    {
        dim3 g(kH / 256, (kB * kS) / 128);
        sgemm_tn256<<<g, 256>>>(p_enc, 2 * kH, W_attn + kH, kG, b_attn,
                                p_ep, kH, kB * kS, kH, 2 * kH, 0);
    }

    // 6. decoder loop
    for (int t = 0; t < kT - 1; t++) {
        float* feat_t = p_feat + (size_t)t * kB * kF;
        dec_pre_gemm<<<64, 256>>>(W_attn, Wh_d, bh_d);
        attn_kernel<<<kB, 256>>>(src, v_attn, feat_t);
        dec_gxw_gemm<<<dim3(kG / 64, 2), 256>>>(Wi_d);
        gru_gate_dec<<<(kB * kH) / 256, 256>>>(p_gxet + (size_t)t * kB * kG,
                                               feat_t);
    }

    // 7. split-convert features, then HMMA output projection
    {
        size_t n = (size_t)kMP * kF;
        cvt_feat_split<<<(unsigned)((n + 255) / 256), 256>>>();
        dim3 g(kMP / outg::BM, kV / outg::BN);  // (16, 250)
        outgemm_kernel<<<g, 256, outg::SMEM_SZ>>>(b_out, out + (size_t)kB * kV);
    }
}

// round 6
// speedup vs baseline: 3.6115x; 1.0945x over previous
#include <cuda_runtime.h>
#include <cuda_bf16.h>
#include <math.h>
#include <stdint.h>

// ---------------------------------------------------------------------------
// Problem constants
// ---------------------------------------------------------------------------
namespace {
constexpr int kS = 48;          // source length
constexpr int kT = 32;          // target length
constexpr int kB = 64;          // batch
constexpr int kH = 1024;        // hidden
constexpr int kE = 512;         // embed
constexpr int kV = 32000;       // vocab
constexpr int kG = 3 * kH;      // 3072 gates
constexpr int kF = 3 * kH + kE; // 3584 out-proj features
constexpr int kXW = kE + 2*kH;  // 2560 decoder GRU input width
constexpr int kPAD = 1;
constexpr int kMR = (kT - 1) * kB; // 1984 output rows
constexpr int kMP = 2048;          // padded rows for tensor GEMM
constexpr int kME = kS * kB;       // 3072 encoder rows
}

// ---------------------------------------------------------------------------
// Packed fp32x2 helpers (FFMA2)
// ---------------------------------------------------------------------------
__device__ __forceinline__ unsigned long long pk2(float x) {
    unsigned long long r;
    unsigned u = __float_as_uint(x);
    asm("mov.b64 %0, {%1, %1};" : "=l"(r) : "r"(u));
    return r;
}
__device__ __forceinline__ void fma2(unsigned long long& d,
                                     unsigned long long a,
                                     unsigned long long b) {
    asm("fma.rn.f32x2 %0, %1, %2, %0;" : "+l"(d) : "l"(a), "l"(b));
}
__device__ __forceinline__ float lo2(unsigned long long v) {
    return __uint_as_float((unsigned)v);
}
__device__ __forceinline__ float hi2(unsigned long long v) {
    return __uint_as_float((unsigned)(v >> 32));
}

// ---------------------------------------------------------------------------
// Plain-PTX helpers: cp.async / ldmatrix / mma.sync
// ---------------------------------------------------------------------------
__device__ __forceinline__ uint32_t smem_u32(const void* p) {
    uint32_t a;
    asm("{ .reg .u64 t; cvta.to.shared.u64 t, %1; cvt.u32.u64 %0, t; }"
        : "=r"(a) : "l"(p));
    return a;
}
#define CP_ASYNC16(dst, src) \
    asm volatile("cp.async.cg.shared.global [%0], [%1], 16;" \
                 :: "r"(dst), "l"(src) : "memory")
#define CP_COMMIT() asm volatile("cp.async.commit_group;" ::: "memory")
#define CP_WAIT1()  asm volatile("cp.async.wait_group 1;" ::: "memory")
#define CP_WAIT0()  asm volatile("cp.async.wait_group 0;" ::: "memory")

__device__ __forceinline__ void ldsm4(uint32_t* r, uint32_t addr) {
    asm volatile("ldmatrix.sync.aligned.m8n8.x4.shared.b16 {%0,%1,%2,%3}, [%4];"
                 : "=r"(r[0]), "=r"(r[1]), "=r"(r[2]), "=r"(r[3])
                 : "r"(addr));
}
__device__ __forceinline__ void mma16816(float* d, const uint32_t* a,
                                         const uint32_t* b) {
    asm volatile(
        "mma.sync.aligned.m16n8k16.row.col.f32.bf16.bf16.f32 "
        "{%0,%1,%2,%3}, {%4,%5,%6,%7}, {%8,%9}, {%0,%1,%2,%3};"
        : "+f"(d[0]), "+f"(d[1]), "+f"(d[2]), "+f"(d[3])
        : "r"(a[0]), "r"(a[1]), "r"(a[2]), "r"(a[3]),
          "r"(b[0]), "r"(b[1]));
}

// ---------------------------------------------------------------------------
// Persistent scratch
// ---------------------------------------------------------------------------
__device__ float g_emb[(size_t)kME * kE];
__device__ float g_gxf[(size_t)kME * kG];
__device__ float g_gxb[(size_t)kME * kG];
__device__ float g_enc[(size_t)kME * 2 * kH];      // [b][s][2H]
__device__ float g_encproj[(size_t)kME * kH];
__device__ float g_h[2][2 * kB * kH];              // double-buffered h_f|h_b
__device__ float g_hcat[kB * 2 * kH];
__device__ float g_hdec[kB * kH];
__device__ float g_hp[2 * kB * kH];                // 2 K-partials
__device__ float g_w[kB * 2 * kH];
__device__ float g_gxp[2 * kB * kG];
__device__ float g_ghd[2 * kB * kG];               // 2 K-partials
__device__ float g_gxet[(size_t)kMR * kG];
__device__ float g_feat[(size_t)kMR * kF];         // [h2, w, et] per step
// bf16 split operands for HMMA GEMMs
__device__ __nv_bfloat16 g_Ahi[(size_t)kMP * kF];  // decoder features
__device__ __nv_bfloat16 g_Alo[(size_t)kMP * kF];
__device__ __nv_bfloat16 g_Bhi[(size_t)kV * kF];   // W_out
__device__ __nv_bfloat16 g_Blo[(size_t)kV * kF];
__device__ __nv_bfloat16 g_Ehi[(size_t)kME * kE];  // encoder embeddings
__device__ __nv_bfloat16 g_Elo[(size_t)kME * kE];
__device__ __nv_bfloat16 g_Wifh[(size_t)kG * kE];  // Wi_f
__device__ __nv_bfloat16 g_Wifl[(size_t)kG * kE];
__device__ __nv_bfloat16 g_Wibh[(size_t)kG * kE];  // Wi_b
__device__ __nv_bfloat16 g_Wibl[(size_t)kG * kE];
__device__ __nv_bfloat16 g_Widh[(size_t)kG * kXW]; // Wi_d (full)
__device__ __nv_bfloat16 g_Widl[(size_t)kG * kXW];
__device__ __nv_bfloat16 g_Wah[(size_t)kH * kG];   // W_attn (full)
__device__ __nv_bfloat16 g_Wal[(size_t)kH * kG];
__device__ __nv_bfloat16 g_Ench[(size_t)kME * 2 * kH];
__device__ __nv_bfloat16 g_Encl[(size_t)kME * 2 * kH];

// ---------------------------------------------------------------------------
__global__ void init_kernel(float* __restrict__ out0) {
    size_t i = (size_t)blockIdx.x * blockDim.x + threadIdx.x;
    if (i < (size_t)kB * kV) out0[i] = 0.f;
    if (i < (size_t)2 * kB * kH) g_h[0][i] = 0.f;
}

// encoder embedding gather + bf16 split emit
__global__ void enc_embed_kernel(const int* __restrict__ src,
                                 const float* __restrict__ table) {
    int row = blockIdx.x;
    int tok = src[row];
    float4 v = ((const float4*)(table + (size_t)tok * kE))[threadIdx.x];
    ((float4*)(g_emb + (size_t)row * kE))[threadIdx.x] = v;
    size_t o = (size_t)row * kE + threadIdx.x * 4;
    float vv[4] = { v.x, v.y, v.z, v.w };
#pragma unroll
    for (int q = 0; q < 4; q++) {
        __nv_bfloat16 h = __float2bfloat16(vv[q]);
        g_Ehi[o + q] = h;
        g_Elo[o + q] = __float2bfloat16(vv[q] - __bfloat162float(h));
    }
}

// decoder embeddings -> feat float + bf16 split into g_Ahi/g_Alo et columns
__global__ void dec_embed_all(const int* __restrict__ trg,
                              const float* __restrict__ emb_dec) {
    int row = blockIdx.x;
    int tok = trg[row];
    float4 v = ((const float4*)(emb_dec + (size_t)tok * kE))[threadIdx.x];
    ((float4*)(g_feat + (size_t)row * kF + 3 * kH))[threadIdx.x] = v;
    size_t o = (size_t)row * kF + 3 * kH + threadIdx.x * 4;
    float vv[4] = { v.x, v.y, v.z, v.w };
#pragma unroll
    for (int q = 0; q < 4; q++) {
        __nv_bfloat16 h = __float2bfloat16(vv[q]);
        g_Ahi[o + q] = h;
        g_Alo[o + q] = __float2bfloat16(vv[q] - __bfloat162float(h));
    }
}

// ---------------------------------------------------------------------------
// bf16 split conversion (2 elements/thread)
// ---------------------------------------------------------------------------
__global__ void cvt_split2(const float* __restrict__ src,
                           __nv_bfloat16* __restrict__ hi,
                           __nv_bfloat16* __restrict__ lo, size_t n2) {
    size_t i = (size_t)blockIdx.x * blockDim.x + threadIdx.x;
    if (i >= n2) return;
    float2 v = ((const float2*)src)[i];
    __nv_bfloat16 h0 = __float2bfloat16(v.x);
    __nv_bfloat16 h1 = __float2bfloat16(v.y);
    __nv_bfloat16 l0 = __float2bfloat16(v.x - __bfloat162float(h0));
    __nv_bfloat16 l1 = __float2bfloat16(v.y - __bfloat162float(h1));
    ((__nv_bfloat162*)hi)[i] = __nv_bfloat162(h0, h1);
    ((__nv_bfloat162*)lo)[i] = __nv_bfloat162(l0, l1);
}

// convert feat columns [0, 3H) for all padded rows
__global__ void cvt_feat_split() {
    size_t i = (size_t)blockIdx.x * blockDim.x + threadIdx.x;
    if (i >= (size_t)kMP * (3 * kH)) return;
    size_t row = i / (3 * kH);
    size_t col = i - row * (3 * kH);
    float v = (row < (size_t)kMR) ? g_feat[row * kF + col] : 0.f;
    __nv_bfloat16 h = __float2bfloat16(v);
    g_Ahi[row * kF + col] = h;
    g_Alo[row * kF + col] = __float2bfloat16(v - __bfloat162float(h));
}

// ---------------------------------------------------------------------------
// Generalized HMMA GEMM (bf16x3 split, fp32 accum):
//   C[M, N] = (Ah+Al)[M,K] * (Bh+Bl)[N,K]^T + bias[N]
// Tile 128x128, K-slab 64, SW128 swizzle, 2-stage cp.async, 8 warps.
// grid.x = M-tile, grid.y = N-tile. A must be readable for 128-row tiles
// (pad M), B for full 128-row tiles. Epilogue guards row < M.
// ---------------------------------------------------------------------------
namespace outg {
constexpr int BM = 128, BN = 128, BK = 64;
constexpr int HALF = 16384;
constexpr int STAGE = 4 * HALF;
constexpr int SMEM_SZ = 2 * STAGE;          // 131072
}

__device__ __forceinline__ void hg_prefetch(
    const __nv_bfloat16* __restrict__ Ah, const __nv_bfloat16* __restrict__ Al,
    int lda,
    const __nv_bfloat16* __restrict__ Bh, const __nv_bfloat16* __restrict__ Bl,
    int ldb, int k0, uint32_t buf, int tid, int m0, int n0) {
    using namespace outg;
#pragma unroll
    for (int i = 0; i < 4; i++) {
        int id = tid + i * 256;
        int row = id >> 3, c = id & 7;
        uint32_t off = (uint32_t)(row << 7) + (c << 4);
        uint32_t sw = off ^ ((off >> 3) & 0x70);
        size_t ga = (size_t)(m0 + row) * lda + k0 + c * 8;
        size_t gb = (size_t)(n0 + row) * ldb + k0 + c * 8;
        CP_ASYNC16(buf + sw, Ah + ga);
        CP_ASYNC16(buf + HALF + sw, Al + ga);
        CP_ASYNC16(buf + 2 * HALF + sw, Bh + gb);
        CP_ASYNC16(buf + 3 * HALF + sw, Bl + gb);
    }
}

__device__ __forceinline__ void hg_compute(uint32_t buf, int lane,
                                           int wm, int wn,
                                           float acc[2][8][4]) {
    using namespace outg;
    const int g = lane >> 3, r = lane & 7;
#pragma unroll
    for (int ks = 0; ks < 4; ks++) {
        uint32_t ahi[2][4], alo[2][4];
#pragma unroll
        for (int mi = 0; mi < 2; mi++) {
            int row = wm + mi * 16 + ((g & 1) << 3) + r;
            int chunk = ks * 2 + (g >> 1);
            uint32_t off = (uint32_t)(row << 7) + (chunk << 4);
            uint32_t sw = off ^ ((off >> 3) & 0x70);
            ldsm4(ahi[mi], buf + sw);
            ldsm4(alo[mi], buf + HALF + sw);
        }
        uint32_t bhi[4][4], blo[4][4];
#pragma unroll
        for (int np = 0; np < 4; np++) {
            int row = wn + np * 16 + ((g >> 1) << 3) + r;
            int chunk = ks * 2 + (g & 1);
            uint32_t off = (uint32_t)(row << 7) + (chunk << 4);
            uint32_t sw = off ^ ((off >> 3) & 0x70);
            ldsm4(bhi[np], buf + 2 * HALF + sw);
            ldsm4(blo[np], buf + 3 * HALF + sw);
        }
#pragma unroll
        for (int mi = 0; mi < 2; mi++) {
#pragma unroll
            for (int np = 0; np < 4; np++) {
#pragma unroll
                for (int a = 0; a < 2; a++) {
                    uint32_t bh[2] = { bhi[np][2 * a], bhi[np][2 * a + 1] };
                    uint32_t bl[2] = { blo[np][2 * a], blo[np][2 * a + 1] };
                    float* d = acc[mi][np * 2 + a];
                    mma16816(d, ahi[mi], bh);
                    mma16816(d, ahi[mi], bl);
                    mma16816(d, alo[mi], bh);
                }
            }
        }
    }
}

__global__ __launch_bounds__(256, 1)
void hgemm(const __nv_bfloat16* __restrict__ Ah,
           const __nv_bfloat16* __restrict__ Al, int lda,
           const __nv_bfloat16* __restrict__ Bh,
           const __nv_bfloat16* __restrict__ Bl, int ldb,
           const float* __restrict__ bias, float* __restrict__ C, int ldc,
           int M, int K) {
    using namespace outg;
    extern __shared__ char smem[];
    const uint32_t sb = smem_u32(smem);
    const int tid = threadIdx.x;
    const int wid = tid >> 5, lane = tid & 31;
    const int m0 = blockIdx.x * BM;
    const int n0 = blockIdx.y * BN;
    const int wm = (wid & 3) * 32;
    const int wn = (wid >> 2) * 64;
    const int nslab = K / BK;

    float acc[2][8][4];
#pragma unroll
    for (int i = 0; i < 2; i++)
#pragma unroll
        for (int j = 0; j < 8; j++)
#pragma unroll
            for (int q = 0; q < 4; q++) acc[i][j][q] = 0.f;

    hg_prefetch(Ah, Al, lda, Bh, Bl, ldb, 0, sb, tid, m0, n0);
    CP_COMMIT();
    hg_prefetch(Ah, Al, lda, Bh, Bl, ldb, BK, sb + STAGE, tid, m0, n0);
    CP_COMMIT();

    for (int s = 0; s < nslab; s++) {
        const int st = s & 1;
        if (s == nslab - 1) { CP_WAIT0(); } else { CP_WAIT1(); }
        __syncthreads();
        hg_compute(sb + st * STAGE, lane, wm, wn, acc);
        __syncthreads();
        if (s + 2 < nslab) {
            hg_prefetch(Ah, Al, lda, Bh, Bl, ldb, (s + 2) * BK,
                        sb + st * STAGE, tid, m0, n0);
            CP_COMMIT();
        }
    }

    const int r0 = m0 + wm + (lane >> 2);
    const int c0 = n0 + wn + (lane & 3) * 2;
#pragma unroll
    for (int mi = 0; mi < 2; mi++) {
#pragma unroll
        for (int ni = 0; ni < 8; ni++) {
            int row = r0 + mi * 16;
            int col = c0 + ni * 8;
            const float* d = acc[mi][ni];
            float b0 = bias[col], b1 = bias[col + 1];
            if (row < M) {
                C[(size_t)row * ldc + col]     = d[0] + b0;
                C[(size_t)row * ldc + col + 1] = d[1] + b1;
            }
            if (row + 8 < M) {
                C[(size_t)(row + 8) * ldc + col]     = d[2] + b0;
                C[(size_t)(row + 8) * ldc + col + 1] = d[3] + b1;
            }
        }
    }
}

// ---------------------------------------------------------------------------
// Fused encoder recurrence step: gh GEMM (gate-triple N-blocking) + GRU gate.
// grid (64 j-tiles of 16 cols, 2 dirs), 256 threads. h double-buffered.
// ---------------------------------------------------------------------------
__global__ __launch_bounds__(256)
void enc_step_fused(int s,
                    const float* __restrict__ Wh_f,
                    const float* __restrict__ Wh_b,
                    const float* __restrict__ bh_f,
                    const float* __restrict__ bh_b) {
    constexpr int BK = 32;
    __shared__ __align__(16) float As[BK][64];
    __shared__ __align__(16) float Bs[BK][48];
    const int tid = threadIdx.x;
    const int dir = blockIdx.y;
    const int j0 = blockIdx.x * 16;
    const float* hread = g_h[s & 1] + dir * (kB * kH);
    float* hwrite = g_h[(s + 1) & 1] + dir * (kB * kH);
    const float* Wh = dir ? Wh_b : Wh_f;
    const float* bh = dir ? bh_b : bh_f;
    const float* gxbase = dir ? g_gxb : g_gxf;
    const int gpos = dir ? (kS - 1 - s) : s;

    const int lr = tid >> 3;          // 0..31
    const int lc = (tid & 7) << 2;    // 0..28
    const int tm = (tid >> 4) << 2;   // 0..60
    const int tn = tid & 15;          // 0..15

    unsigned long long acc[2][3];
#pragma unroll
    for (int p = 0; p < 2; p++)
#pragma unroll
        for (int q = 0; q < 3; q++) acc[p][q] = 0ull;

    for (int k0 = 0; k0 < kH; k0 += BK) {
#pragma unroll
        for (int h = 0; h < 2; h++) {
            int r = lr + h * 32;
            float4 v = *(const float4*)(hread + (size_t)r * kH + k0 + lc);
            As[lc + 0][r] = v.x; As[lc + 1][r] = v.y;
            As[lc + 2][r] = v.z; As[lc + 3][r] = v.w;
        }
#pragma unroll
        for (int h = 0; h < 2; h++) {
            int idx = tid + h * 256;
            if (idx < 384) {
                int rr = idx >> 3;             // 0..47
                int cc = (idx & 7) << 2;
                int sec = rr >> 4, wi = rr & 15;
                float4 w = *(const float4*)(Wh +
                    (size_t)(sec * kH + j0 + wi) * kH + k0 + cc);
                Bs[cc + 0][rr] = w.x; Bs[cc + 1][rr] = w.y;
                Bs[cc + 2][rr] = w.z; Bs[cc + 3][rr] = w.w;
            }
        }
        __syncthreads();
#pragma unroll
        for (int k = 0; k < BK; k++) {
            ulonglong2 av = *(const ulonglong2*)&As[k][tm];
            unsigned long long b0 = pk2(Bs[k][tn]);
            unsigned long long b1 = pk2(Bs[k][16 + tn]);
            unsigned long long b2 = pk2(Bs[k][32 + tn]);
            fma2(acc[0][0], av.x, b0); fma2(acc[1][0], av.y, b0);
            fma2(acc[0][1], av.x, b1); fma2(acc[1][1], av.y, b1);
            fma2(acc[0][2], av.x, b2); fma2(acc[1][2], av.y, b2);
        }
        __syncthreads();
    }

    const int j = j0 + tn;
    const float bhr = bh[j], bhz = bh[kH + j], bhn = bh[2 * kH + j];
#pragma unroll
    for (int i = 0; i < 4; i++) {
        int b = tm + i;
        float ghr = (i & 1) ? hi2(acc[i >> 1][0]) : lo2(acc[i >> 1][0]);
        float ghz = (i & 1) ? hi2(acc[i >> 1][1]) : lo2(acc[i >> 1][1]);
        float ghn = (i & 1) ? hi2(acc[i >> 1][2]) : lo2(acc[i >> 1][2]);
        ghr += bhr; ghz += bhz; ghn += bhn;
        const float* gx = gxbase + ((size_t)gpos * kB + b) * kG;
        float r = 1.f / (1.f + expf(-(gx[j] + ghr)));
        float z = 1.f / (1.f + expf(-(gx[kH + j] + ghz)));
        float n = tanhf(gx[2 * kH + j] + r * ghn);
        float hold = hread[(size_t)b * kH + j];
        float h2 = (1.f - z) * n + z * hold;
        hwrite[(size_t)b * kH + j] = h2;
        g_enc[((size_t)b * kS + gpos) * (2 * kH) + dir * kH + j] = h2;
    }
}

// ---------------------------------------------------------------------------
// Small-M GEMM body (FFMA2) — used by decoder GEMMs + W_fc
// ---------------------------------------------------------------------------
__device__ __forceinline__
void gemm64_body(const float* __restrict__ A, int lda,
                 const float* __restrict__ Bm, int ldb,
                 const float* __restrict__ bias,
                 float* __restrict__ C, int ldc,
                 int K, int act, int nb) {
    constexpr int BK = 32;
    __shared__ __align__(16) float As[BK][64];
    __shared__ __align__(16) float Bs[BK][64];
    const int tid = threadIdx.x;
    const int bn = nb * 64;
    const int lr = tid >> 3;
    const int lc = (tid & 7) << 2;
    const int tm = (tid >> 4) << 2;
    const int tn = (tid & 15) << 2;

    unsigned long long acc[4][2];
#pragma unroll
    for (int i = 0; i < 4; i++) { acc[i][0] = 0ull; acc[i][1] = 0ull; }

    for (int k0 = 0; k0 < K; k0 += BK) {
#pragma unroll
        for (int h = 0; h < 2; h++) {
            int r = lr + h * 32;
            float4 v = *(const float4*)(A + (size_t)r * lda + k0 + lc);
            As[lc + 0][r] = v.x; As[lc + 1][r] = v.y;
            As[lc + 2][r] = v.z; As[lc + 3][r] = v.w;
            float4 w = *(const float4*)(Bm + (size_t)(bn + r) * ldb + k0 + lc);
            Bs[lc + 0][r] = w.x; Bs[lc + 1][r] = w.y;
            Bs[lc + 2][r] = w.z; Bs[lc + 3][r] = w.w;
        }
        __syncthreads();
#pragma unroll
        for (int k = 0; k < BK; k++) {
            float4 af = *(const float4*)&As[k][tm];
            unsigned long long aa[4];
            aa[0] = pk2(af.x); aa[1] = pk2(af.y);
            aa[2] = pk2(af.z); aa[3] = pk2(af.w);
            ulonglong2 bv = *(const ulonglong2*)&Bs[k][tn];
#pragma unroll
            for (int i = 0; i < 4; i++) {
                fma2(acc[i][0], aa[i], bv.x);
                fma2(acc[i][1], aa[i], bv.y);
            }
        }
        __syncthreads();
    }
#pragma unroll
    for (int i = 0; i < 4; i++) {
        int col = bn + tn;
        float4 v;
        v.x = lo2(acc[i][0]); v.y = hi2(acc[i][0]);
        v.z = lo2(acc[i][1]); v.w = hi2(acc[i][1]);
        if (bias) {
            v.x += bias[col + 0]; v.y += bias[col + 1];
            v.z += bias[col + 2]; v.w += bias[col + 3];
        }
        if (act == 1) {
            v.x = tanhf(v.x); v.y = tanhf(v.y);
            v.z = tanhf(v.z); v.w = tanhf(v.w);
        }
        *(float4*)(C + (size_t)(tm + i) * ldc + col) = v;
    }
}

__global__ __launch_bounds__(256)
void gemm64(const float* __restrict__ A, int lda,
            const float* __restrict__ Bm, int ldb,
            const float* __restrict__ bias,
            float* __restrict__ C, int ldc, int K, int act) {
    gemm64_body(A, lda, Bm, ldb, bias, C, ldc, K, act, blockIdx.x);
}

// Decoder pre-attention GEMMs, K-split 2: hp (32 blocks) + ghd (96 blocks)
__global__ __launch_bounds__(256)
void dec_pre_gemm(const float* __restrict__ W_attn,
                  const float* __restrict__ Wh_d,
                  const float* __restrict__ bh_d) {
    int x = blockIdx.x;
    if (x < 32) {
        int ks = x >> 4, nb = x & 15;
        gemm64_body(g_hdec + ks * 512, kH, W_attn + ks * 512, kG, nullptr,
                    g_hp + (size_t)ks * kB * kH, kH, 512, 0, nb);
    } else {
        int i = x - 32;
        int ks = i / 48, nb = i % 48;
        gemm64_body(g_hdec + ks * 512, kH, Wh_d + ks * 512, kH,
                    ks == 0 ? bh_d : nullptr,
                    g_ghd + (size_t)ks * kB * kG, kG, 512, 0, nb);
    }
}

// Decoder w-gate GEMM: K split in 2. grid (48, 2)
__global__ __launch_bounds__(256)
void dec_gxw_gemm(const float* __restrict__ Wi_d) {
    int ks = blockIdx.y;
    gemm64_body(g_w + ks * 1024, 2 * kH,
                Wi_d + kE + ks * 1024, kXW, nullptr,
                g_gxp + (size_t)ks * kB * kG, kG, 1024, 0, blockIdx.x);
}

// ---------------------------------------------------------------------------
__global__ void hcat_kernel() {
    int idx = blockIdx.x * blockDim.x + threadIdx.x;
    if (idx >= 2 * kB * kH) return;
    int dir = idx / (kB * kH);
    int rem = idx - dir * (kB * kH);
    int b = rem / kH, j = rem - b * kH;
    g_hcat[(size_t)b * 2 * kH + dir * kH + j] = g_h[0][idx];
}

__global__ __launch_bounds__(256)
void attn_kernel(const int* __restrict__ src,
                 const float* __restrict__ v_attn,
                 float* __restrict__ feat_t) {
    int b = blockIdx.x;
    __shared__ float sc[kS];
    int tid = threadIdx.x, warp = tid >> 5, lane = tid & 31;
    const float* hp0 = g_hp + (size_t)b * kH;
    const float* hp1 = g_hp + (size_t)kB * kH + (size_t)b * kH;

    for (int s = warp; s < kS; s += 8) {
        const float* ep = g_encproj + ((size_t)b * kS + s) * kH;
        float p = 0.f;
        for (int j = lane; j < kH; j += 32)
            p += v_attn[j] * tanhf(hp0[j] + hp1[j] + ep[j]);
#pragma unroll
        for (int o = 16; o; o >>= 1) p += __shfl_xor_sync(0xffffffffu, p, o);
        if (lane == 0) sc[s] = (src[s * kB + b] != kPAD) ? p : -1e10f;
    }
    __syncthreads();

    if (tid < 32) {
        float v1 = sc[tid];
        float v2 = (tid + 32 < kS) ? sc[tid + 32] : -1e30f;
        float mx = fmaxf(v1, v2);
#pragma unroll
        for (int o = 16; o; o >>= 1) mx = fmaxf(mx, __shfl_xor_sync(0xffffffffu, mx, o));
        float e1 = expf(v1 - mx);
        float e2 = (tid + 32 < kS) ? expf(v2 - mx) : 0.f;
        float sm = e1 + e2;
#pragma unroll
        for (int o = 16; o; o >>= 1) sm += __shfl_xor_sync(0xffffffffu, sm, o);
        float inv = 1.f / sm;
        sc[tid] = e1 * inv;
        if (tid + 32 < kS) sc[tid + 32] = e2 * inv;
    }
    __syncthreads();

    for (int c = tid; c < 2 * kH; c += 256) {
        float acc = 0.f;
#pragma unroll 8
        for (int s = 0; s < kS; s++)
            acc += sc[s] * g_enc[((size_t)b * kS + s) * (2 * kH) + c];
        g_w[(size_t)b * 2 * kH + c] = acc;
        feat_t[(size_t)b * kF + kH + c] = acc;
    }
}

__global__ void gru_gate_dec(const float* __restrict__ gxet,
                             float* __restrict__ feat_t) {
    int idx = blockIdx.x * blockDim.x + threadIdx.x;
    if (idx >= kB * kH) return;
    int b = idx / kH, j = idx - b * kH;
    size_t o = (size_t)b * kG;
    const float* gx = gxet + o;
    const float* p0 = g_gxp + o;
    const float* p1 = g_gxp + (size_t)kB * kG + o;
    const float* q0 = g_ghd + o;
    const float* q1 = g_ghd + (size_t)kB * kG + o;
    float h = g_hdec[idx];
    float xr = gx[j] + p0[j] + p1[j];
    float xz = gx[kH + j] + p0[kH + j] + p1[kH + j];
    float xn = gx[2 * kH + j] + p0[2 * kH + j] + p1[2 * kH + j];
    float ghr = q0[j] + q1[j];
    float ghz = q0[kH + j] + q1[kH + j];
    float ghn = q0[2 * kH + j] + q1[2 * kH + j];
    float r = 1.f / (1.f + expf(-(xr + ghr)));
    float z = 1.f / (1.f + expf(-(xz + ghz)));
    float n = tanhf(xn + r * ghn);
    float h2 = (1.f - z) * n + z * h;
    g_hdec[idx] = h2;
    feat_t[(size_t)b * kF + j] = h2;
}

// ---------------------------------------------------------------------------
// Host orchestration
// ---------------------------------------------------------------------------
extern "C" void kernel_launch(void* const* d_in, const int* in_sizes, int n_in,
                              void* d_out, int out_size) {
    const int*   src     = (const int*)d_in[0];
    const int*   trg     = (const int*)d_in[1];
    const float* emb_enc = (const float*)d_in[2];
    const float* Wi_f    = (const float*)d_in[3];
    const float* Wh_f    = (const float*)d_in[4];
    const float* bi_f    = (const float*)d_in[5];
    const float* bh_f    = (const float*)d_in[6];
    const float* Wi_b    = (const float*)d_in[7];
    const float* Wh_b    = (const float*)d_in[8];
    const float* bi_b    = (const float*)d_in[9];
    const float* bh_b    = (const float*)d_in[10];
    const float* W_fc    = (const float*)d_in[11];
    const float* b_fc    = (const float*)d_in[12];
    const float* W_attn  = (const float*)d_in[13];
    const float* b_attn  = (const float*)d_in[14];
    const float* v_attn  = (const float*)d_in[15];
    const float* emb_dec = (const float*)d_in[16];
    const float* Wi_d    = (const float*)d_in[17];
    const float* Wh_d    = (const float*)d_in[18];
    const float* bi_d    = (const float*)d_in[19];
    const float* bh_d    = (const float*)d_in[20];
    const float* W_out   = (const float*)d_in[21];
    const float* b_out   = (const float*)d_in[22];
    float* out = (float*)d_out;

    float *p_enc, *p_ep, *p_hcat, *p_hdec, *p_gxet, *p_feat, *p_gxf, *p_gxb;
    __nv_bfloat16 *p_Ahi, *p_Alo, *p_Bhi, *p_Blo, *p_Ehi, *p_Elo;
    __nv_bfloat16 *p_Wifh, *p_Wifl, *p_Wibh, *p_Wibl;
    __nv_bfloat16 *p_Widh, *p_Widl, *p_Wah, *p_Wal, *p_Ench, *p_Encl;
    cudaGetSymbolAddress((void**)&p_enc, g_enc);
    cudaGetSymbolAddress((void**)&p_ep, g_encproj);
    cudaGetSymbolAddress((void**)&p_hcat, g_hcat);
    cudaGetSymbolAddress((void**)&p_hdec, g_hdec);
    cudaGetSymbolAddress((void**)&p_gxet, g_gxet);
    cudaGetSymbolAddress((void**)&p_feat, g_feat);
    cudaGetSymbolAddress((void**)&p_gxf, g_gxf);
    cudaGetSymbolAddress((void**)&p_gxb, g_gxb);
    cudaGetSymbolAddress((void**)&p_Ahi, g_Ahi);
    cudaGetSymbolAddress((void**)&p_Alo, g_Alo);
    cudaGetSymbolAddress((void**)&p_Bhi, g_Bhi);
    cudaGetSymbolAddress((void**)&p_Blo, g_Blo);
    cudaGetSymbolAddress((void**)&p_Ehi, g_Ehi);
    cudaGetSymbolAddress((void**)&p_Elo, g_Elo);
    cudaGetSymbolAddress((void**)&p_Wifh, g_Wifh);
    cudaGetSymbolAddress((void**)&p_Wifl, g_Wifl);
    cudaGetSymbolAddress((void**)&p_Wibh, g_Wibh);
    cudaGetSymbolAddress((void**)&p_Wibl, g_Wibl);
    cudaGetSymbolAddress((void**)&p_Widh, g_Widh);
    cudaGetSymbolAddress((void**)&p_Widl, g_Widl);
    cudaGetSymbolAddress((void**)&p_Wah, g_Wah);
    cudaGetSymbolAddress((void**)&p_Wal, g_Wal);
    cudaGetSymbolAddress((void**)&p_Ench, g_Ench);
    cudaGetSymbolAddress((void**)&p_Encl, g_Encl);

    cudaFuncSetAttribute(hgemm,
                         cudaFuncAttributeMaxDynamicSharedMemorySize,
                         outg::SMEM_SZ);

    // 0. zero output timestep 0 + encoder hidden buffer 0
    init_kernel<<<((size_t)kB * kV + 255) / 256, 256>>>(out);

    // 0b. weight split conversions (independent of everything else)
    {
        size_t n2;
        n2 = (size_t)kV * kF / 2;
        cvt_split2<<<(unsigned)((n2 + 255) / 256), 256>>>(W_out, p_Bhi, p_Blo, n2);
        n2 = (size_t)kG * kE / 2;
        cvt_split2<<<(unsigned)((n2 + 255) / 256), 256>>>(Wi_f, p_Wifh, p_Wifl, n2);
        cvt_split2<<<(unsigned)((n2 + 255) / 256), 256>>>(Wi_b, p_Wibh, p_Wibl, n2);
        n2 = (size_t)kG * kXW / 2;
        cvt_split2<<<(unsigned)((n2 + 255) / 256), 256>>>(Wi_d, p_Widh, p_Widl, n2);
        n2 = (size_t)kH * kG / 2;
        cvt_split2<<<(unsigned)((n2 + 255) / 256), 256>>>(W_attn, p_Wah, p_Wal, n2);
    }

    // 1. embedding gathers (emit bf16 splits inline)
    enc_embed_kernel<<<kME, 128>>>(src, emb_enc);
    dec_embed_all<<<kMR, 128>>>(trg, emb_dec);

    // 2. batched input-gate GEMMs (HMMA)
    hgemm<<<dim3(kME / 128, kG / 128), 256, outg::SMEM_SZ>>>(
        p_Ehi, p_Elo, kE, p_Wifh, p_Wifl, kE, bi_f, p_gxf, kG, kME, kE);
    hgemm<<<dim3(kME / 128, kG / 128), 256, outg::SMEM_SZ>>>(
        p_Ehi, p_Elo, kE, p_Wibh, p_Wibl, kE, bi_b, p_gxb, kG, kME, kE);
    hgemm<<<dim3(kMP / 128, kG / 128), 256, outg::SMEM_SZ>>>(
        p_Ahi + 3 * kH, p_Alo + 3 * kH, kF, p_Widh, p_Widl, kXW, bi_d,
        p_gxet, kG, kMR, kE);

    // 3. encoder recurrence: one fused kernel per step
    for (int s = 0; s < kS; s++)
        enc_step_fused<<<dim3(64, 2), 256>>>(s, Wh_f, Wh_b, bh_f, bh_b);

    // 4. decoder init hidden
    hcat_kernel<<<(2 * kB * kH) / 256, 256>>>();
    gemm64<<<kH / 64, 256>>>(p_hcat, 2 * kH, W_fc, 2 * kH, b_fc,
                             p_hdec, kH, 2 * kH, 1);

    // 5. encoder split + attention projection (HMMA)
    {
        size_t n2 = (size_t)kME * 2 * kH / 2;
        cvt_split2<<<(unsigned)((n2 + 255) / 256), 256>>>(p_enc, p_Ench, p_Encl, n2);
        hgemm<<<dim3(kME / 128, kH / 128), 256, outg::SMEM_SZ>>>(
            p_Ench, p_Encl, 2 * kH, p_Wah + kH, p_Wal + kH, kG, b_attn,
            p_ep, kH, kME, 2 * kH);
    }

    // 6. decoder loop
    for (int t = 0; t < kT - 1; t++) {
        float* feat_t = p_feat + (size_t)t * kB * kF;
        dec_pre_gemm<<<128, 256>>>(W_attn, Wh_d, bh_d);
        attn_kernel<<<kB, 256>>>(src, v_attn, feat_t);
        dec_gxw_gemm<<<dim3(kG / 64, 2), 256>>>(Wi_d);
        gru_gate_dec<<<(kB * kH) / 256, 256>>>(p_gxet + (size_t)t * kB * kG,
                                               feat_t);
    }

    // 7. split-convert features, HMMA output projection
    {
        size_t n = (size_t)kMP * (3 * kH);
        cvt_feat_split<<<(unsigned)((n + 255) / 256), 256>>>();
        hgemm<<<dim3(kMP / 128, kV / 128), 256, outg::SMEM_SZ>>>(
            p_Ahi, p_Alo, kF, p_Bhi, p_Blo, kF, b_out,
            out + (size_t)kB * kV, kV, kMR, kF);
    }
}

// round 7
// speedup vs baseline: 3.8578x; 1.0682x over previous
#include <cuda_runtime.h>
#include <cuda_bf16.h>
#include <math.h>
#include <stdint.h>

// ---------------------------------------------------------------------------
// Problem constants
// ---------------------------------------------------------------------------
namespace {
constexpr int kS = 48;          // source length
constexpr int kT = 32;          // target length
constexpr int kB = 64;          // batch
constexpr int kH = 1024;        // hidden
constexpr int kE = 512;         // embed
constexpr int kV = 32000;       // vocab
constexpr int kG = 3 * kH;      // 3072 gates
constexpr int kF = 3 * kH + kE; // 3584 out-proj features
constexpr int kXW = kE + 2*kH;  // 2560 decoder GRU input width
constexpr int kPAD = 1;
constexpr int kMR = (kT - 1) * kB; // 1984 output rows
constexpr int kMP = 2048;          // padded rows for tensor GEMM
constexpr int kME = kS * kB;       // 3072 encoder rows
}

// ---------------------------------------------------------------------------
// Packed fp32x2 helpers (FFMA2)
// ---------------------------------------------------------------------------
__device__ __forceinline__ unsigned long long pk2(float x) {
    unsigned long long r;
    unsigned u = __float_as_uint(x);
    asm("mov.b64 %0, {%1, %1};" : "=l"(r) : "r"(u));
    return r;
}
__device__ __forceinline__ void fma2(unsigned long long& d,
                                     unsigned long long a,
                                     unsigned long long b) {
    asm("fma.rn.f32x2 %0, %1, %2, %0;" : "+l"(d) : "l"(a), "l"(b));
}
__device__ __forceinline__ float lo2(unsigned long long v) {
    return __uint_as_float((unsigned)v);
}
__device__ __forceinline__ float hi2(unsigned long long v) {
    return __uint_as_float((unsigned)(v >> 32));
}

// ---------------------------------------------------------------------------
// Plain-PTX helpers: cp.async / ldmatrix / mma.sync
// ---------------------------------------------------------------------------
__device__ __forceinline__ uint32_t smem_u32(const void* p) {
    uint32_t a;
    asm("{ .reg .u64 t; cvta.to.shared.u64 t, %1; cvt.u32.u64 %0, t; }"
        : "=r"(a) : "l"(p));
    return a;
}
#define CP_ASYNC16(dst, src) \
    asm volatile("cp.async.cg.shared.global [%0], [%1], 16;" \
                 :: "r"(dst), "l"(src) : "memory")
#define CP_COMMIT() asm volatile("cp.async.commit_group;" ::: "memory")
#define CP_WAIT1()  asm volatile("cp.async.wait_group 1;" ::: "memory")
#define CP_WAIT0()  asm volatile("cp.async.wait_group 0;" ::: "memory")

__device__ __forceinline__ void ldsm4(uint32_t* r, uint32_t addr) {
    asm volatile("ldmatrix.sync.aligned.m8n8.x4.shared.b16 {%0,%1,%2,%3}, [%4];"
                 : "=r"(r[0]), "=r"(r[1]), "=r"(r[2]), "=r"(r[3])
                 : "r"(addr));
}
__device__ __forceinline__ void mma16816(float* d, const uint32_t* a,
                                         const uint32_t* b) {
    asm volatile(
        "mma.sync.aligned.m16n8k16.row.col.f32.bf16.bf16.f32 "
        "{%0,%1,%2,%3}, {%4,%5,%6,%7}, {%8,%9}, {%0,%1,%2,%3};"
        : "+f"(d[0]), "+f"(d[1]), "+f"(d[2]), "+f"(d[3])
        : "r"(a[0]), "r"(a[1]), "r"(a[2]), "r"(a[3]),
          "r"(b[0]), "r"(b[1]));
}

// ---------------------------------------------------------------------------
// Persistent scratch
// ---------------------------------------------------------------------------
__device__ float g_emb[(size_t)kME * kE];
__device__ float g_gxf[(size_t)kME * kG];
__device__ float g_gxb[(size_t)kME * kG];
__device__ float g_enc[(size_t)kME * 2 * kH];      // [b][s][2H]
__device__ float g_encproj[(size_t)kME * kH];
__device__ float g_encWi[(size_t)kME * kG];        // enc @ Wi_d[:,E:]^T
__device__ float g_h[2][2 * kB * kH];              // double-buffered h_f|h_b
__device__ float g_hcat[kB * 2 * kH];
__device__ float g_hdec[kB * kH];
__device__ float g_hp[2 * kB * kH];                // 2 K-partials
__device__ float g_ghd[2 * kB * kG];               // 2 K-partials
__device__ float g_gxet[(size_t)kMR * kG];
__device__ float g_feat[(size_t)kMR * kF];         // [h2, w, et] per step
// bf16 split operands for HMMA GEMMs
__device__ __nv_bfloat16 g_Ahi[(size_t)kMP * kF];  // decoder features
__device__ __nv_bfloat16 g_Alo[(size_t)kMP * kF];
__device__ __nv_bfloat16 g_Bhi[(size_t)kV * kF];   // W_out
__device__ __nv_bfloat16 g_Blo[(size_t)kV * kF];
__device__ __nv_bfloat16 g_Ehi[(size_t)kME * kE];  // encoder embeddings
__device__ __nv_bfloat16 g_Elo[(size_t)kME * kE];
__device__ __nv_bfloat16 g_Wifh[(size_t)kG * kE];  // Wi_f
__device__ __nv_bfloat16 g_Wifl[(size_t)kG * kE];
__device__ __nv_bfloat16 g_Wibh[(size_t)kG * kE];  // Wi_b
__device__ __nv_bfloat16 g_Wibl[(size_t)kG * kE];
__device__ __nv_bfloat16 g_Widh[(size_t)kG * kXW]; // Wi_d (full)
__device__ __nv_bfloat16 g_Widl[(size_t)kG * kXW];
__device__ __nv_bfloat16 g_Wah[(size_t)kH * kG];   // W_attn (full)
__device__ __nv_bfloat16 g_Wal[(size_t)kH * kG];
__device__ __nv_bfloat16 g_Ench[(size_t)kME * 2 * kH];
__device__ __nv_bfloat16 g_Encl[(size_t)kME * 2 * kH];

// ---------------------------------------------------------------------------
__global__ void init_kernel(float* __restrict__ out0) {
    size_t i = (size_t)blockIdx.x * blockDim.x + threadIdx.x;
    if (i < (size_t)kB * kV) out0[i] = 0.f;
    if (i < (size_t)2 * kB * kH) g_h[0][i] = 0.f;
}

// encoder embedding gather + bf16 split emit
__global__ void enc_embed_kernel(const int* __restrict__ src,
                                 const float* __restrict__ table) {
    int row = blockIdx.x;
    int tok = src[row];
    float4 v = ((const float4*)(table + (size_t)tok * kE))[threadIdx.x];
    ((float4*)(g_emb + (size_t)row * kE))[threadIdx.x] = v;
    size_t o = (size_t)row * kE + threadIdx.x * 4;
    float vv[4] = { v.x, v.y, v.z, v.w };
#pragma unroll
    for (int q = 0; q < 4; q++) {
        __nv_bfloat16 h = __float2bfloat16(vv[q]);
        g_Ehi[o + q] = h;
        g_Elo[o + q] = __float2bfloat16(vv[q] - __bfloat162float(h));
    }
}

// decoder embeddings -> feat float + bf16 split into g_Ahi/g_Alo et columns
__global__ void dec_embed_all(const int* __restrict__ trg,
                              const float* __restrict__ emb_dec) {
    int row = blockIdx.x;
    int tok = trg[row];
    float4 v = ((const float4*)(emb_dec + (size_t)tok * kE))[threadIdx.x];
    ((float4*)(g_feat + (size_t)row * kF + 3 * kH))[threadIdx.x] = v;
    size_t o = (size_t)row * kF + 3 * kH + threadIdx.x * 4;
    float vv[4] = { v.x, v.y, v.z, v.w };
#pragma unroll
    for (int q = 0; q < 4; q++) {
        __nv_bfloat16 h = __float2bfloat16(vv[q]);
        g_Ahi[o + q] = h;
        g_Alo[o + q] = __float2bfloat16(vv[q] - __bfloat162float(h));
    }
}

// ---------------------------------------------------------------------------
// bf16 split conversion (4 elements/thread, fully vectorized)
// ---------------------------------------------------------------------------
__global__ void cvt_split4(const float4* __restrict__ src,
                           __nv_bfloat162* __restrict__ hi,
                           __nv_bfloat162* __restrict__ lo, size_t n4) {
    size_t i = (size_t)blockIdx.x * blockDim.x + threadIdx.x;
    if (i >= n4) return;
    float4 v = src[i];
    __nv_bfloat16 h0 = __float2bfloat16(v.x);
    __nv_bfloat16 h1 = __float2bfloat16(v.y);
    __nv_bfloat16 h2 = __float2bfloat16(v.z);
    __nv_bfloat16 h3 = __float2bfloat16(v.w);
    hi[2 * i]     = __nv_bfloat162(h0, h1);
    hi[2 * i + 1] = __nv_bfloat162(h2, h3);
    lo[2 * i]     = __nv_bfloat162(
        __float2bfloat16(v.x - __bfloat162float(h0)),
        __float2bfloat16(v.y - __bfloat162float(h1)));
    lo[2 * i + 1] = __nv_bfloat162(
        __float2bfloat16(v.z - __bfloat162float(h2)),
        __float2bfloat16(v.w - __bfloat162float(h3)));
}

// convert feat columns [0, 3H) for all padded rows
__global__ void cvt_feat_split() {
    size_t i = (size_t)blockIdx.x * blockDim.x + threadIdx.x;
    if (i >= (size_t)kMP * (3 * kH) / 4) return;
    size_t row = i / (3 * kH / 4);
    size_t col = (i - row * (3 * kH / 4)) * 4;
    float4 v = make_float4(0.f, 0.f, 0.f, 0.f);
    if (row < (size_t)kMR)
        v = *(const float4*)(g_feat + row * kF + col);
    size_t o = row * kF + col;
    float vv[4] = { v.x, v.y, v.z, v.w };
#pragma unroll
    for (int q = 0; q < 4; q++) {
        __nv_bfloat16 h = __float2bfloat16(vv[q]);
        g_Ahi[o + q] = h;
        g_Alo[o + q] = __float2bfloat16(vv[q] - __bfloat162float(h));
    }
}

// ---------------------------------------------------------------------------
// Generalized HMMA GEMM (bf16x3 split, fp32 accum)
// ---------------------------------------------------------------------------
namespace outg {
constexpr int BM = 128, BN = 128, BK = 64;
constexpr int HALF = 16384;
constexpr int STAGE = 4 * HALF;
constexpr int SMEM_SZ = 2 * STAGE;          // 131072
}

__device__ __forceinline__ void hg_prefetch(
    const __nv_bfloat16* __restrict__ Ah, const __nv_bfloat16* __restrict__ Al,
    int lda,
    const __nv_bfloat16* __restrict__ Bh, const __nv_bfloat16* __restrict__ Bl,
    int ldb, int k0, uint32_t buf, int tid, int m0, int n0) {
    using namespace outg;
#pragma unroll
    for (int i = 0; i < 4; i++) {
        int id = tid + i * 256;
        int row = id >> 3, c = id & 7;
        uint32_t off = (uint32_t)(row << 7) + (c << 4);
        uint32_t sw = off ^ ((off >> 3) & 0x70);
        size_t ga = (size_t)(m0 + row) * lda + k0 + c * 8;
        size_t gb = (size_t)(n0 + row) * ldb + k0 + c * 8;
        CP_ASYNC16(buf + sw, Ah + ga);
        CP_ASYNC16(buf + HALF + sw, Al + ga);
        CP_ASYNC16(buf + 2 * HALF + sw, Bh + gb);
        CP_ASYNC16(buf + 3 * HALF + sw, Bl + gb);
    }
}

__device__ __forceinline__ void hg_compute(uint32_t buf, int lane,
                                           int wm, int wn,
                                           float acc[2][8][4]) {
    using namespace outg;
    const int g = lane >> 3, r = lane & 7;
#pragma unroll
    for (int ks = 0; ks < 4; ks++) {
        uint32_t ahi[2][4], alo[2][4];
#pragma unroll
        for (int mi = 0; mi < 2; mi++) {
            int row = wm + mi * 16 + ((g & 1) << 3) + r;
            int chunk = ks * 2 + (g >> 1);
            uint32_t off = (uint32_t)(row << 7) + (chunk << 4);
            uint32_t sw = off ^ ((off >> 3) & 0x70);
            ldsm4(ahi[mi], buf + sw);
            ldsm4(alo[mi], buf + HALF + sw);
        }
        uint32_t bhi[4][4], blo[4][4];
#pragma unroll
        for (int np = 0; np < 4; np++) {
            int row = wn + np * 16 + ((g >> 1) << 3) + r;
            int chunk = ks * 2 + (g & 1);
            uint32_t off = (uint32_t)(row << 7) + (chunk << 4);
            uint32_t sw = off ^ ((off >> 3) & 0x70);
            ldsm4(bhi[np], buf + 2 * HALF + sw);
            ldsm4(blo[np], buf + 3 * HALF + sw);
        }
#pragma unroll
        for (int mi = 0; mi < 2; mi++) {
#pragma unroll
            for (int np = 0; np < 4; np++) {
#pragma unroll
                for (int a = 0; a < 2; a++) {
                    uint32_t bh[2] = { bhi[np][2 * a], bhi[np][2 * a + 1] };
                    uint32_t bl[2] = { blo[np][2 * a], blo[np][2 * a + 1] };
                    float* d = acc[mi][np * 2 + a];
                    mma16816(d, ahi[mi], bh);
                    mma16816(d, ahi[mi], bl);
                    mma16816(d, alo[mi], bh);
                }
            }
        }
    }
}

__global__ __launch_bounds__(256, 1)
void hgemm(const __nv_bfloat16* __restrict__ Ah,
           const __nv_bfloat16* __restrict__ Al, int lda,
           const __nv_bfloat16* __restrict__ Bh,
           const __nv_bfloat16* __restrict__ Bl, int ldb,
           const float* __restrict__ bias, float* __restrict__ C, int ldc,
           int M, int K) {
    using namespace outg;
    extern __shared__ char smem[];
    const uint32_t sb = smem_u32(smem);
    const int tid = threadIdx.x;
    const int wid = tid >> 5, lane = tid & 31;
    const int m0 = blockIdx.x * BM;
    const int n0 = blockIdx.y * BN;
    const int wm = (wid & 3) * 32;
    const int wn = (wid >> 2) * 64;
    const int nslab = K / BK;

    float acc[2][8][4];
#pragma unroll
    for (int i = 0; i < 2; i++)
#pragma unroll
        for (int j = 0; j < 8; j++)
#pragma unroll
            for (int q = 0; q < 4; q++) acc[i][j][q] = 0.f;

    hg_prefetch(Ah, Al, lda, Bh, Bl, ldb, 0, sb, tid, m0, n0);
    CP_COMMIT();
    hg_prefetch(Ah, Al, lda, Bh, Bl, ldb, BK, sb + STAGE, tid, m0, n0);
    CP_COMMIT();

    for (int s = 0; s < nslab; s++) {
        const int st = s & 1;
        if (s == nslab - 1) { CP_WAIT0(); } else { CP_WAIT1(); }
        __syncthreads();
        hg_compute(sb + st * STAGE, lane, wm, wn, acc);
        __syncthreads();
        if (s + 2 < nslab) {
            hg_prefetch(Ah, Al, lda, Bh, Bl, ldb, (s + 2) * BK,
                        sb + st * STAGE, tid, m0, n0);
            CP_COMMIT();
        }
    }

    const int r0 = m0 + wm + (lane >> 2);
    const int c0 = n0 + wn + (lane & 3) * 2;
#pragma unroll
    for (int mi = 0; mi < 2; mi++) {
#pragma unroll
        for (int ni = 0; ni < 8; ni++) {
            int row = r0 + mi * 16;
            int col = c0 + ni * 8;
            const float* d = acc[mi][ni];
            float b0 = bias ? bias[col] : 0.f;
            float b1 = bias ? bias[col + 1] : 0.f;
            if (row < M) {
                C[(size_t)row * ldc + col]     = d[0] + b0;
                C[(size_t)row * ldc + col + 1] = d[1] + b1;
            }
            if (row + 8 < M) {
                C[(size_t)(row + 8) * ldc + col]     = d[2] + b0;
                C[(size_t)(row + 8) * ldc + col + 1] = d[3] + b1;
            }
        }
    }
}

// ---------------------------------------------------------------------------
// Fused encoder recurrence step (unchanged from round 6)
// ---------------------------------------------------------------------------
__global__ __launch_bounds__(256)
void enc_step_fused(int s,
                    const float* __restrict__ Wh_f,
                    const float* __restrict__ Wh_b,
                    const float* __restrict__ bh_f,
                    const float* __restrict__ bh_b) {
    constexpr int BK = 32;
    __shared__ __align__(16) float As[BK][64];
    __shared__ __align__(16) float Bs[BK][48];
    const int tid = threadIdx.x;
    const int dir = blockIdx.y;
    const int j0 = blockIdx.x * 16;
    const float* hread = g_h[s & 1] + dir * (kB * kH);
    float* hwrite = g_h[(s + 1) & 1] + dir * (kB * kH);
    const float* Wh = dir ? Wh_b : Wh_f;
    const float* bh = dir ? bh_b : bh_f;
    const float* gxbase = dir ? g_gxb : g_gxf;
    const int gpos = dir ? (kS - 1 - s) : s;

    const int lr = tid >> 3;
    const int lc = (tid & 7) << 2;
    const int tm = (tid >> 4) << 2;
    const int tn = tid & 15;

    unsigned long long acc[2][3];
#pragma unroll
    for (int p = 0; p < 2; p++)
#pragma unroll
        for (int q = 0; q < 3; q++) acc[p][q] = 0ull;

    for (int k0 = 0; k0 < kH; k0 += BK) {
#pragma unroll
        for (int h = 0; h < 2; h++) {
            int r = lr + h * 32;
            float4 v = *(const float4*)(hread + (size_t)r * kH + k0 + lc);
            As[lc + 0][r] = v.x; As[lc + 1][r] = v.y;
            As[lc + 2][r] = v.z; As[lc + 3][r] = v.w;
        }
#pragma unroll
        for (int h = 0; h < 2; h++) {
            int idx = tid + h * 256;
            if (idx < 384) {
                int rr = idx >> 3;
                int cc = (idx & 7) << 2;
                int sec = rr >> 4, wi = rr & 15;
                float4 w = *(const float4*)(Wh +
                    (size_t)(sec * kH + j0 + wi) * kH + k0 + cc);
                Bs[cc + 0][rr] = w.x; Bs[cc + 1][rr] = w.y;
                Bs[cc + 2][rr] = w.z; Bs[cc + 3][rr] = w.w;
            }
        }
        __syncthreads();
#pragma unroll
        for (int k = 0; k < BK; k++) {
            ulonglong2 av = *(const ulonglong2*)&As[k][tm];
            unsigned long long b0 = pk2(Bs[k][tn]);
            unsigned long long b1 = pk2(Bs[k][16 + tn]);
            unsigned long long b2 = pk2(Bs[k][32 + tn]);
            fma2(acc[0][0], av.x, b0); fma2(acc[1][0], av.y, b0);
            fma2(acc[0][1], av.x, b1); fma2(acc[1][1], av.y, b1);
            fma2(acc[0][2], av.x, b2); fma2(acc[1][2], av.y, b2);
        }
        __syncthreads();
    }

    const int j = j0 + tn;
    const float bhr = bh[j], bhz = bh[kH + j], bhn = bh[2 * kH + j];
#pragma unroll
    for (int i = 0; i < 4; i++) {
        int b = tm + i;
        float ghr = (i & 1) ? hi2(acc[i >> 1][0]) : lo2(acc[i >> 1][0]);
        float ghz = (i & 1) ? hi2(acc[i >> 1][1]) : lo2(acc[i >> 1][1]);
        float ghn = (i & 1) ? hi2(acc[i >> 1][2]) : lo2(acc[i >> 1][2]);
        ghr += bhr; ghz += bhz; ghn += bhn;
        const float* gx = gxbase + ((size_t)gpos * kB + b) * kG;
        float r = 1.f / (1.f + expf(-(gx[j] + ghr)));
        float z = 1.f / (1.f + expf(-(gx[kH + j] + ghz)));
        float n = tanhf(gx[2 * kH + j] + r * ghn);
        float hold = hread[(size_t)b * kH + j];
        float h2 = (1.f - z) * n + z * hold;
        hwrite[(size_t)b * kH + j] = h2;
        g_enc[((size_t)b * kS + gpos) * (2 * kH) + dir * kH + j] = h2;
    }
}

// ---------------------------------------------------------------------------
// Small-M GEMM body (FFMA2)
// ---------------------------------------------------------------------------
__device__ __forceinline__
void gemm64_body(const float* __restrict__ A, int lda,
                 const float* __restrict__ Bm, int ldb,
                 const float* __restrict__ bias,
                 float* __restrict__ C, int ldc,
                 int K, int act, int nb) {
    constexpr int BK = 32;
    __shared__ __align__(16) float As[BK][64];
    __shared__ __align__(16) float Bs[BK][64];
    const int tid = threadIdx.x;
    const int bn = nb * 64;
    const int lr = tid >> 3;
    const int lc = (tid & 7) << 2;
    const int tm = (tid >> 4) << 2;
    const int tn = (tid & 15) << 2;

    unsigned long long acc[4][2];
#pragma unroll
    for (int i = 0; i < 4; i++) { acc[i][0] = 0ull; acc[i][1] = 0ull; }

    for (int k0 = 0; k0 < K; k0 += BK) {
#pragma unroll
        for (int h = 0; h < 2; h++) {
            int r = lr + h * 32;
            float4 v = *(const float4*)(A + (size_t)r * lda + k0 + lc);
            As[lc + 0][r] = v.x; As[lc + 1][r] = v.y;
            As[lc + 2][r] = v.z; As[lc + 3][r] = v.w;
            float4 w = *(const float4*)(Bm + (size_t)(bn + r) * ldb + k0 + lc);
            Bs[lc + 0][r] = w.x; Bs[lc + 1][r] = w.y;
            Bs[lc + 2][r] = w.z; Bs[lc + 3][r] = w.w;
        }
        __syncthreads();
#pragma unroll
        for (int k = 0; k < BK; k++) {
            float4 af = *(const float4*)&As[k][tm];
            unsigned long long aa[4];
            aa[0] = pk2(af.x); aa[1] = pk2(af.y);
            aa[2] = pk2(af.z); aa[3] = pk2(af.w);
            ulonglong2 bv = *(const ulonglong2*)&Bs[k][tn];
#pragma unroll
            for (int i = 0; i < 4; i++) {
                fma2(acc[i][0], aa[i], bv.x);
                fma2(acc[i][1], aa[i], bv.y);
            }
        }
        __syncthreads();
    }
#pragma unroll
    for (int i = 0; i < 4; i++) {
        int col = bn + tn;
        float4 v;
        v.x = lo2(acc[i][0]); v.y = hi2(acc[i][0]);
        v.z = lo2(acc[i][1]); v.w = hi2(acc[i][1]);
        if (bias) {
            v.x += bias[col + 0]; v.y += bias[col + 1];
            v.z += bias[col + 2]; v.w += bias[col + 3];
        }
        if (act == 1) {
            v.x = tanhf(v.x); v.y = tanhf(v.y);
            v.z = tanhf(v.z); v.w = tanhf(v.w);
        }
        *(float4*)(C + (size_t)(tm + i) * ldc + col) = v;
    }
}

__global__ __launch_bounds__(256)
void gemm64(const float* __restrict__ A, int lda,
            const float* __restrict__ Bm, int ldb,
            const float* __restrict__ bias,
            float* __restrict__ C, int ldc, int K, int act) {
    gemm64_body(A, lda, Bm, ldb, bias, C, ldc, K, act, blockIdx.x);
}

// Decoder pre-attention GEMMs, K-split 2: hp (32 blocks) + ghd (96 blocks)
__global__ __launch_bounds__(256)
void dec_pre_gemm(const float* __restrict__ W_attn,
                  const float* __restrict__ Wh_d,
                  const float* __restrict__ bh_d) {
    int x = blockIdx.x;
    if (x < 32) {
        int ks = x >> 4, nb = x & 15;
        gemm64_body(g_hdec + ks * 512, kH, W_attn + ks * 512, kG, nullptr,
                    g_hp + (size_t)ks * kB * kH, kH, 512, 0, nb);
    } else {
        int i = x - 32;
        int ks = i / 48, nb = i % 48;
        gemm64_body(g_hdec + ks * 512, kH, Wh_d + ks * 512, kH,
                    ks == 0 ? bh_d : nullptr,
                    g_ghd + (size_t)ks * kB * kG, kG, 512, 0, nb);
    }
}

// ---------------------------------------------------------------------------
__global__ void hcat_kernel() {
    int idx = blockIdx.x * blockDim.x + threadIdx.x;
    if (idx >= 2 * kB * kH) return;
    int dir = idx / (kB * kH);
    int rem = idx - dir * (kB * kH);
    int b = rem / kH, j = rem - b * kH;
    g_hcat[(size_t)b * 2 * kH + dir * kH + j] = g_h[0][idx];
}

// ---------------------------------------------------------------------------
// Fully fused decoder step (post pre-GEMM): scores -> softmax -> context w
// -> gxw = a @ encWi -> GRU gate -> h2/feat writes. One block per batch b.
// ---------------------------------------------------------------------------
__global__ __launch_bounds__(256)
void attn_step_fused(const int* __restrict__ src,
                     const float* __restrict__ v_attn,
                     const float* __restrict__ gxet_t,
                     float* __restrict__ feat_t) {
    int b = blockIdx.x;
    __shared__ float sc[kS];
    __shared__ float sgxw[kG];
    int tid = threadIdx.x, warp = tid >> 5, lane = tid & 31;
    const float* hp0 = g_hp + (size_t)b * kH;
    const float* hp1 = g_hp + (size_t)kB * kH + (size_t)b * kH;

    // 1. attention scores
    for (int s = warp; s < kS; s += 8) {
        const float* ep = g_encproj + ((size_t)b * kS + s) * kH;
        float p = 0.f;
        for (int j = lane; j < kH; j += 32)
            p += v_attn[j] * tanhf(hp0[j] + hp1[j] + ep[j]);
#pragma unroll
        for (int o = 16; o; o >>= 1) p += __shfl_xor_sync(0xffffffffu, p, o);
        if (lane == 0) sc[s] = (src[s * kB + b] != kPAD) ? p : -1e10f;
    }
    __syncthreads();

    // 2. softmax over S=48
    if (tid < 32) {
        float v1 = sc[tid];
        float v2 = (tid + 32 < kS) ? sc[tid + 32] : -1e30f;
        float mx = fmaxf(v1, v2);
#pragma unroll
        for (int o = 16; o; o >>= 1) mx = fmaxf(mx, __shfl_xor_sync(0xffffffffu, mx, o));
        float e1 = expf(v1 - mx);
        float e2 = (tid + 32 < kS) ? expf(v2 - mx) : 0.f;
        float sm = e1 + e2;
#pragma unroll
        for (int o = 16; o; o >>= 1) sm += __shfl_xor_sync(0xffffffffu, sm, o);
        float inv = 1.f / sm;
        sc[tid] = e1 * inv;
        if (tid + 32 < kS) sc[tid + 32] = e2 * inv;
    }
    __syncthreads();

    // 3a. context w = a @ enc  (2048 cols, float4 per thread iter)
    for (int c4 = tid; c4 < 2 * kH / 4; c4 += 256) {
        float4 acc = make_float4(0.f, 0.f, 0.f, 0.f);
        const float4* base = (const float4*)(g_enc + (size_t)b * kS * 2 * kH) + c4;
#pragma unroll 8
        for (int s = 0; s < kS; s++) {
            float a = sc[s];
            float4 e = base[s * (2 * kH / 4)];
            acc.x += a * e.x; acc.y += a * e.y;
            acc.z += a * e.z; acc.w += a * e.w;
        }
        ((float4*)(feat_t + (size_t)b * kF + kH))[c4] = acc;
    }
    // 3b. gxw = a @ encWi  (3072 cols -> smem)
    for (int c4 = tid; c4 < kG / 4; c4 += 256) {
        float4 acc = make_float4(0.f, 0.f, 0.f, 0.f);
        const float4* base = (const float4*)(g_encWi + (size_t)b * kS * kG) + c4;
#pragma unroll 8
        for (int s = 0; s < kS; s++) {
            float a = sc[s];
            float4 e = base[s * (kG / 4)];
            acc.x += a * e.x; acc.y += a * e.y;
            acc.z += a * e.z; acc.w += a * e.w;
        }
        *(float4*)(sgxw + c4 * 4) = acc;
    }
    __syncthreads();

    // 4. GRU gate -> h2
    const float* q0 = g_ghd + (size_t)b * kG;
    const float* q1 = g_ghd + (size_t)kB * kG + (size_t)b * kG;
    const float* gx = gxet_t + (size_t)b * kG;
    for (int j = tid; j < kH; j += 256) {
        float h = g_hdec[(size_t)b * kH + j];
        float xr = gx[j] + sgxw[j];
        float xz = gx[kH + j] + sgxw[kH + j];
        float xn = gx[2 * kH + j] + sgxw[2 * kH + j];
        float ghr = q0[j] + q1[j];
        float ghz = q0[kH + j] + q1[kH + j];
        float ghn = q0[2 * kH + j] + q1[2 * kH + j];
        float r = 1.f / (1.f + expf(-(xr + ghr)));
        float z = 1.f / (1.f + expf(-(xz + ghz)));
        float n = tanhf(xn + r * ghn);
        float h2 = (1.f - z) * n + z * h;
        g_hdec[(size_t)b * kH + j] = h2;
        feat_t[(size_t)b * kF + j] = h2;
    }
}

// ---------------------------------------------------------------------------
// Host orchestration
// ---------------------------------------------------------------------------
extern "C" void kernel_launch(void* const* d_in, const int* in_sizes, int n_in,
                              void* d_out, int out_size) {
    const int*   src     = (const int*)d_in[0];
    const int*   trg     = (const int*)d_in[1];
    const float* emb_enc = (const float*)d_in[2];
    const float* Wi_f    = (const float*)d_in[3];
    const float* Wh_f    = (const float*)d_in[4];
    const float* bi_f    = (const float*)d_in[5];
    const float* bh_f    = (const float*)d_in[6];
    const float* Wi_b    = (const float*)d_in[7];
    const float* Wh_b    = (const float*)d_in[8];
    const float* bi_b    = (const float*)d_in[9];
    const float* bh_b    = (const float*)d_in[10];
    const float* W_fc    = (const float*)d_in[11];
    const float* b_fc    = (const float*)d_in[12];
    const float* W_attn  = (const float*)d_in[13];
    const float* b_attn  = (const float*)d_in[14];
    const float* v_attn  = (const float*)d_in[15];
    const float* emb_dec = (const float*)d_in[16];
    const float* Wi_d    = (const float*)d_in[17];
    const float* Wh_d    = (const float*)d_in[18];
    const float* bi_d    = (const float*)d_in[19];
    const float* bh_d    = (const float*)d_in[20];
    const float* W_out   = (const float*)d_in[21];
    const float* b_out   = (const float*)d_in[22];
    float* out = (float*)d_out;

    float *p_enc, *p_ep, *p_encWi, *p_hcat, *p_hdec, *p_gxet, *p_feat,
          *p_gxf, *p_gxb;
    __nv_bfloat16 *p_Ahi, *p_Alo, *p_Bhi, *p_Blo, *p_Ehi, *p_Elo;
    __nv_bfloat16 *p_Wifh, *p_Wifl, *p_Wibh, *p_Wibl;
    __nv_bfloat16 *p_Widh, *p_Widl, *p_Wah, *p_Wal, *p_Ench, *p_Encl;
    cudaGetSymbolAddress((void**)&p_enc, g_enc);
    cudaGetSymbolAddress((void**)&p_ep, g_encproj);
    cudaGetSymbolAddress((void**)&p_encWi, g_encWi);
    cudaGetSymbolAddress((void**)&p_hcat, g_hcat);
    cudaGetSymbolAddress((void**)&p_hdec, g_hdec);
    cudaGetSymbolAddress((void**)&p_gxet, g_gxet);
    cudaGetSymbolAddress((void**)&p_feat, g_feat);
    cudaGetSymbolAddress((void**)&p_gxf, g_gxf);
    cudaGetSymbolAddress((void**)&p_gxb, g_gxb);
    cudaGetSymbolAddress((void**)&p_Ahi, g_Ahi);
    cudaGetSymbolAddress((void**)&p_Alo, g_Alo);
    cudaGetSymbolAddress((void**)&p_Bhi, g_Bhi);
    cudaGetSymbolAddress((void**)&p_Blo, g_Blo);
    cudaGetSymbolAddress((void**)&p_Ehi, g_Ehi);
    cudaGetSymbolAddress((void**)&p_Elo, g_Elo);
    cudaGetSymbolAddress((void**)&p_Wifh, g_Wifh);
    cudaGetSymbolAddress((void**)&p_Wifl, g_Wifl);
    cudaGetSymbolAddress((void**)&p_Wibh, g_Wibh);
    cudaGetSymbolAddress((void**)&p_Wibl, g_Wibl);
    cudaGetSymbolAddress((void**)&p_Widh, g_Widh);
    cudaGetSymbolAddress((void**)&p_Widl, g_Widl);
    cudaGetSymbolAddress((void**)&p_Wah, g_Wah);
    cudaGetSymbolAddress((void**)&p_Wal, g_Wal);
    cudaGetSymbolAddress((void**)&p_Ench, g_Ench);
    cudaGetSymbolAddress((void**)&p_Encl, g_Encl);

    cudaFuncSetAttribute(hgemm,
                         cudaFuncAttributeMaxDynamicSharedMemorySize,
                         outg::SMEM_SZ);

    // 0. zero output timestep 0 + encoder hidden buffer 0
    init_kernel<<<((size_t)kB * kV + 255) / 256, 256>>>(out);

    // 0b. weight split conversions (vectorized)
    {
        size_t n4;
        n4 = (size_t)kV * kF / 4;
        cvt_split4<<<(unsigned)((n4 + 255) / 256), 256>>>(
            (const float4*)W_out, (__nv_bfloat162*)p_Bhi,
            (__nv_bfloat162*)p_Blo, n4);
        n4 = (size_t)kG * kE / 4;
        cvt_split4<<<(unsigned)((n4 + 255) / 256), 256>>>(
            (const float4*)Wi_f, (__nv_bfloat162*)p_Wifh,
            (__nv_bfloat162*)p_Wifl, n4);
        cvt_split4<<<(unsigned)((n4 + 255) / 256), 256>>>(
            (const float4*)Wi_b, (__nv_bfloat162*)p_Wibh,
            (__nv_bfloat162*)p_Wibl, n4);
        n4 = (size_t)kG * kXW / 4;
        cvt_split4<<<(unsigned)((n4 + 255) / 256), 256>>>(
            (const float4*)Wi_d, (__nv_bfloat162*)p_Widh,
            (__nv_bfloat162*)p_Widl, n4);
        n4 = (size_t)kH * kG / 4;
        cvt_split4<<<(unsigned)((n4 + 255) / 256), 256>>>(
            (const float4*)W_attn, (__nv_bfloat162*)p_Wah,
            (__nv_bfloat162*)p_Wal, n4);
    }

    // 1. embedding gathers (emit bf16 splits inline)
    enc_embed_kernel<<<kME, 128>>>(src, emb_enc);
    dec_embed_all<<<kMR, 128>>>(trg, emb_dec);

    // 2. batched input-gate GEMMs (HMMA)
    hgemm<<<dim3(kME / 128, kG / 128), 256, outg::SMEM_SZ>>>(
        p_Ehi, p_Elo, kE, p_Wifh, p_Wifl, kE, bi_f, p_gxf, kG, kME, kE);
    hgemm<<<dim3(kME / 128, kG / 128), 256, outg::SMEM_SZ>>>(
        p_Ehi, p_Elo, kE, p_Wibh, p_Wibl, kE, bi_b, p_gxb, kG, kME, kE);
    hgemm<<<dim3(kMP / 128, kG / 128), 256, outg::SMEM_SZ>>>(
        p_Ahi + 3 * kH, p_Alo + 3 * kH, kF, p_Widh, p_Widl, kXW, bi_d,
        p_gxet, kG, kMR, kE);

    // 3. encoder recurrence
    for (int s = 0; s < kS; s++)
        enc_step_fused<<<dim3(64, 2), 256>>>(s, Wh_f, Wh_b, bh_f, bh_b);

    // 4. decoder init hidden
    hcat_kernel<<<(2 * kB * kH) / 256, 256>>>();
    gemm64<<<kH / 64, 256>>>(p_hcat, 2 * kH, W_fc, 2 * kH, b_fc,
                             p_hdec, kH, 2 * kH, 1);

    // 5. encoder split + attention projection + encWi precompute (HMMA)
    {
        size_t n4 = (size_t)kME * 2 * kH / 4;
        cvt_split4<<<(unsigned)((n4 + 255) / 256), 256>>>(
            (const float4*)p_enc, (__nv_bfloat162*)p_Ench,
            (__nv_bfloat162*)p_Encl, n4);
        hgemm<<<dim3(kME / 128, kH / 128), 256, outg::SMEM_SZ>>>(
            p_Ench, p_Encl, 2 * kH, p_Wah + kH, p_Wal + kH, kG, b_attn,
            p_ep, kH, kME, 2 * kH);
        hgemm<<<dim3(kME / 128, kG / 128), 256, outg::SMEM_SZ>>>(
            p_Ench, p_Encl, 2 * kH, p_Widh + kE, p_Widl + kE, kXW,
            (const float*)nullptr, p_encWi, kG, kME, 2 * kH);
    }

    // 6. decoder loop: 2 launches per step
    for (int t = 0; t < kT - 1; t++) {
        float* feat_t = p_feat + (size_t)t * kB * kF;
        dec_pre_gemm<<<128, 256>>>(W_attn, Wh_d, bh_d);
        attn_step_fused<<<kB, 256>>>(src, v_attn,
                                     p_gxet + (size_t)t * kB * kG, feat_t);
    }

    // 7. split-convert features, HMMA output projection
    {
        size_t n = (size_t)kMP * (3 * kH) / 4;
        cvt_feat_split<<<(unsigned)((n + 255) / 256), 256>>>();
        hgemm<<<dim3(kMP / 128, kV / 128), 256, outg::SMEM_SZ>>>(
            p_Ahi, p_Alo, kF, p_Bhi, p_Blo, kF, b_out,
            out + (size_t)kB * kV, kV, kMR, kF);
    }
}

// round 9
// speedup vs baseline: 4.2249x; 1.0952x over previous
#include <cuda_runtime.h>
#include <cuda_bf16.h>
#include <math.h>
#include <stdint.h>

// ---------------------------------------------------------------------------
// Problem constants
// ---------------------------------------------------------------------------
namespace {
constexpr int kS = 48;          // source length
constexpr int kT = 32;          // target length
constexpr int kB = 64;          // batch
constexpr int kH = 1024;        // hidden
constexpr int kE = 512;         // embed
constexpr int kV = 32000;       // vocab
constexpr int kG = 3 * kH;      // 3072 gates
constexpr int kF = 3 * kH + kE; // 3584 out-proj features
constexpr int kXW = kE + 2*kH;  // 2560 decoder GRU input width
constexpr int kPAD = 1;
constexpr int kMR = (kT - 1) * kB; // 1984 output rows
constexpr int kMP = 2048;          // padded rows for tensor GEMM
constexpr int kME = kS * kB;       // 3072 encoder rows
}

// ---------------------------------------------------------------------------
// Packed fp32x2 helpers (FFMA2)
// ---------------------------------------------------------------------------
__device__ __forceinline__ unsigned long long pk2(float x) {
    unsigned long long r;
    unsigned u = __float_as_uint(x);
    asm("mov.b64 %0, {%1, %1};" : "=l"(r) : "r"(u));
    return r;
}
__device__ __forceinline__ void fma2(unsigned long long& d,
                                     unsigned long long a,
                                     unsigned long long b) {
    asm("fma.rn.f32x2 %0, %1, %2, %0;" : "+l"(d) : "l"(a), "l"(b));
}
__device__ __forceinline__ float lo2(unsigned long long v) {
    return __uint_as_float((unsigned)v);
}
__device__ __forceinline__ float hi2(unsigned long long v) {
    return __uint_as_float((unsigned)(v >> 32));
}

// ---------------------------------------------------------------------------
// Plain-PTX helpers: cp.async / ldmatrix / mma.sync
// ---------------------------------------------------------------------------
__device__ __forceinline__ uint32_t smem_u32(const void* p) {
    uint32_t a;
    asm("{ .reg .u64 t; cvta.to.shared.u64 t, %1; cvt.u32.u64 %0, t; }"
        : "=r"(a) : "l"(p));
    return a;
}
#define CP_ASYNC16(dst, src) \
    asm volatile("cp.async.cg.shared.global [%0], [%1], 16;" \
                 :: "r"(dst), "l"(src) : "memory")
#define CP_COMMIT() asm volatile("cp.async.commit_group;" ::: "memory")
#define CP_WAIT1()  asm volatile("cp.async.wait_group 1;" ::: "memory")
#define CP_WAIT0()  asm volatile("cp.async.wait_group 0;" ::: "memory")

__device__ __forceinline__ void ldsm4(uint32_t* r, uint32_t addr) {
    asm volatile("ldmatrix.sync.aligned.m8n8.x4.shared.b16 {%0,%1,%2,%3}, [%4];"
                 : "=r"(r[0]), "=r"(r[1]), "=r"(r[2]), "=r"(r[3])
                 : "r"(addr));
}
__device__ __forceinline__ void mma16816(float* d, const uint32_t* a,
                                         const uint32_t* b) {
    asm volatile(
        "mma.sync.aligned.m16n8k16.row.col.f32.bf16.bf16.f32 "
        "{%0,%1,%2,%3}, {%4,%5,%6,%7}, {%8,%9}, {%0,%1,%2,%3};"
        : "+f"(d[0]), "+f"(d[1]), "+f"(d[2]), "+f"(d[3])
        : "r"(a[0]), "r"(a[1]), "r"(a[2]), "r"(a[3]),
          "r"(b[0]), "r"(b[1]));
}

// ---------------------------------------------------------------------------
// Persistent scratch
// ---------------------------------------------------------------------------
__device__ float g_emb[(size_t)kME * kE];
__device__ float g_gxf[(size_t)kME * kG];
__device__ float g_gxb[(size_t)kME * kG];
__device__ float g_enc[(size_t)kME * 2 * kH];      // [b][s][2H]
__device__ float g_encproj[(size_t)kME * kH];
__device__ float g_encWi[(size_t)kME * kG];        // enc @ Wi_d[:,E:]^T
__device__ float g_h[2][2 * kB * kH];              // double-buffered h_f|h_b
__device__ float g_hcat[kB * 2 * kH];
__device__ float g_hdec[kB * kH];
__device__ float g_hp[2 * kB * kH];                // 2 K-partials
__device__ float g_ghd[2 * kB * kG];               // 2 K-partials
__device__ float g_gxet[(size_t)kMR * kG];
__device__ float g_feat[(size_t)kMR * kF];         // [h2, w, et] per step
// bf16 split operands for HMMA GEMMs
__device__ __nv_bfloat16 g_Ahi[(size_t)kMP * kF];  // decoder features
__device__ __nv_bfloat16 g_Alo[(size_t)kMP * kF];
__device__ __nv_bfloat16 g_Bhi[(size_t)kV * kF];   // W_out
__device__ __nv_bfloat16 g_Blo[(size_t)kV * kF];
__device__ __nv_bfloat16 g_Ehi[(size_t)kME * kE];  // encoder embeddings
__device__ __nv_bfloat16 g_Elo[(size_t)kME * kE];
__device__ __nv_bfloat16 g_Wifh[(size_t)kG * kE];  // Wi_f
__device__ __nv_bfloat16 g_Wifl[(size_t)kG * kE];
__device__ __nv_bfloat16 g_Wibh[(size_t)kG * kE];  // Wi_b
__device__ __nv_bfloat16 g_Wibl[(size_t)kG * kE];
__device__ __nv_bfloat16 g_Widh[(size_t)kG * kXW]; // Wi_d (full)
__device__ __nv_bfloat16 g_Widl[(size_t)kG * kXW];
__device__ __nv_bfloat16 g_Wah[(size_t)kH * kG];   // W_attn (full)
__device__ __nv_bfloat16 g_Wal[(size_t)kH * kG];
__device__ __nv_bfloat16 g_Ench[(size_t)kME * 2 * kH];
__device__ __nv_bfloat16 g_Encl[(size_t)kME * 2 * kH];

// ---------------------------------------------------------------------------
__global__ void init_kernel(float* __restrict__ out0) {
    size_t i = (size_t)blockIdx.x * blockDim.x + threadIdx.x;
    if (i < (size_t)kB * kV) out0[i] = 0.f;
    if (i < (size_t)2 * kB * kH) g_h[0][i] = 0.f;
}

// encoder embedding gather + bf16 split emit
__global__ void enc_embed_kernel(const int* __restrict__ src,
                                 const float* __restrict__ table) {
    int row = blockIdx.x;
    int tok = src[row];
    float4 v = ((const float4*)(table + (size_t)tok * kE))[threadIdx.x];
    ((float4*)(g_emb + (size_t)row * kE))[threadIdx.x] = v;
    size_t o = (size_t)row * kE + threadIdx.x * 4;
    float vv[4] = { v.x, v.y, v.z, v.w };
#pragma unroll
    for (int q = 0; q < 4; q++) {
        __nv_bfloat16 h = __float2bfloat16(vv[q]);
        g_Ehi[o + q] = h;
        g_Elo[o + q] = __float2bfloat16(vv[q] - __bfloat162float(h));
    }
}

// decoder embeddings -> feat float + bf16 split into g_Ahi/g_Alo et columns
__global__ void dec_embed_all(const int* __restrict__ trg,
                              const float* __restrict__ emb_dec) {
    int row = blockIdx.x;
    int tok = trg[row];
    float4 v = ((const float4*)(emb_dec + (size_t)tok * kE))[threadIdx.x];
    ((float4*)(g_feat + (size_t)row * kF + 3 * kH))[threadIdx.x] = v;
    size_t o = (size_t)row * kF + 3 * kH + threadIdx.x * 4;
    float vv[4] = { v.x, v.y, v.z, v.w };
#pragma unroll
    for (int q = 0; q < 4; q++) {
        __nv_bfloat16 h = __float2bfloat16(vv[q]);
        g_Ahi[o + q] = h;
        g_Alo[o + q] = __float2bfloat16(vv[q] - __bfloat162float(h));
    }
}

// ---------------------------------------------------------------------------
// bf16 split conversion (4 elements/thread, fully vectorized)
// ---------------------------------------------------------------------------
__global__ void cvt_split4(const float4* __restrict__ src,
                           __nv_bfloat162* __restrict__ hi,
                           __nv_bfloat162* __restrict__ lo, size_t n4) {
    size_t i = (size_t)blockIdx.x * blockDim.x + threadIdx.x;
    if (i >= n4) return;
    float4 v = src[i];
    __nv_bfloat16 h0 = __float2bfloat16(v.x);
    __nv_bfloat16 h1 = __float2bfloat16(v.y);
    __nv_bfloat16 h2 = __float2bfloat16(v.z);
    __nv_bfloat16 h3 = __float2bfloat16(v.w);
    hi[2 * i]     = __nv_bfloat162(h0, h1);
    hi[2 * i + 1] = __nv_bfloat162(h2, h3);
    lo[2 * i]     = __nv_bfloat162(
        __float2bfloat16(v.x - __bfloat162float(h0)),
        __float2bfloat16(v.y - __bfloat162float(h1)));
    lo[2 * i + 1] = __nv_bfloat162(
        __float2bfloat16(v.z - __bfloat162float(h2)),
        __float2bfloat16(v.w - __bfloat162float(h3)));
}

// convert feat columns [0, 3H) for all padded rows
__global__ void cvt_feat_split() {
    size_t i = (size_t)blockIdx.x * blockDim.x + threadIdx.x;
    if (i >= (size_t)kMP * (3 * kH) / 4) return;
    size_t row = i / (3 * kH / 4);
    size_t col = (i - row * (3 * kH / 4)) * 4;
    float4 v = make_float4(0.f, 0.f, 0.f, 0.f);
    if (row < (size_t)kMR)
        v = *(const float4*)(g_feat + row * kF + col);
    size_t o = row * kF + col;
    float vv[4] = { v.x, v.y, v.z, v.w };
#pragma unroll
    for (int q = 0; q < 4; q++) {
        __nv_bfloat16 h = __float2bfloat16(vv[q]);
        g_Ahi[o + q] = h;
        g_Alo[o + q] = __float2bfloat16(vv[q] - __bfloat162float(h));
    }
}

// ---------------------------------------------------------------------------
// Generalized HMMA GEMM (bf16x3 split, fp32 accum)
// ---------------------------------------------------------------------------
namespace outg {
constexpr int BM = 128, BN = 128, BK = 64;
constexpr int HALF = 16384;
constexpr int STAGE = 4 * HALF;
constexpr int SMEM_SZ = 2 * STAGE;          // 131072
}

__device__ __forceinline__ void hg_prefetch(
    const __nv_bfloat16* __restrict__ Ah, const __nv_bfloat16* __restrict__ Al,
    int lda,
    const __nv_bfloat16* __restrict__ Bh, const __nv_bfloat16* __restrict__ Bl,
    int ldb, int k0, uint32_t buf, int tid, int m0, int n0) {
    using namespace outg;
#pragma unroll
    for (int i = 0; i < 4; i++) {
        int id = tid + i * 256;
        int row = id >> 3, c = id & 7;
        uint32_t off = (uint32_t)(row << 7) + (c << 4);
        uint32_t sw = off ^ ((off >> 3) & 0x70);
        size_t ga = (size_t)(m0 + row) * lda + k0 + c * 8;
        size_t gb = (size_t)(n0 + row) * ldb + k0 + c * 8;
        CP_ASYNC16(buf + sw, Ah + ga);
        CP_ASYNC16(buf + HALF + sw, Al + ga);
        CP_ASYNC16(buf + 2 * HALF + sw, Bh + gb);
        CP_ASYNC16(buf + 3 * HALF + sw, Bl + gb);
    }
}

__device__ __forceinline__ void hg_compute(uint32_t buf, int lane,
                                           int wm, int wn,
                                           float acc[2][8][4]) {
    using namespace outg;
    const int g = lane >> 3, r = lane & 7;
#pragma unroll
    for (int ks = 0; ks < 4; ks++) {
        uint32_t ahi[2][4], alo[2][4];
#pragma unroll
        for (int mi = 0; mi < 2; mi++) {
            int row = wm + mi * 16 + ((g & 1) << 3) + r;
            int chunk = ks * 2 + (g >> 1);
            uint32_t off = (uint32_t)(row << 7) + (chunk << 4);
            uint32_t sw = off ^ ((off >> 3) & 0x70);
            ldsm4(ahi[mi], buf + sw);
            ldsm4(alo[mi], buf + HALF + sw);
        }
        uint32_t bhi[4][4], blo[4][4];
#pragma unroll
        for (int np = 0; np < 4; np++) {
            int row = wn + np * 16 + ((g >> 1) << 3) + r;
            int chunk = ks * 2 + (g & 1);
            uint32_t off = (uint32_t)(row << 7) + (chunk << 4);
            uint32_t sw = off ^ ((off >> 3) & 0x70);
            ldsm4(bhi[np], buf + 2 * HALF + sw);
            ldsm4(blo[np], buf + 3 * HALF + sw);
        }
#pragma unroll
        for (int mi = 0; mi < 2; mi++) {
#pragma unroll
            for (int np = 0; np < 4; np++) {
#pragma unroll
                for (int a = 0; a < 2; a++) {
                    uint32_t bh[2] = { bhi[np][2 * a], bhi[np][2 * a + 1] };
                    uint32_t bl[2] = { blo[np][2 * a], blo[np][2 * a + 1] };
                    float* d = acc[mi][np * 2 + a];
                    mma16816(d, ahi[mi], bh);
                    mma16816(d, ahi[mi], bl);
                    mma16816(d, alo[mi], bh);
                }
            }
        }
    }
}

__global__ __launch_bounds__(256, 1)
void hgemm(const __nv_bfloat16* __restrict__ Ah,
           const __nv_bfloat16* __restrict__ Al, int lda,
           const __nv_bfloat16* __restrict__ Bh,
           const __nv_bfloat16* __restrict__ Bl, int ldb,
           const float* __restrict__ bias, float* __restrict__ C, int ldc,
           int M, int K) {
    using namespace outg;
    extern __shared__ char smem[];
    const uint32_t sb = smem_u32(smem);
    const int tid = threadIdx.x;
    const int wid = tid >> 5, lane = tid & 31;
    const int m0 = blockIdx.x * BM;
    const int n0 = blockIdx.y * BN;
    const int wm = (wid & 3) * 32;
    const int wn = (wid >> 2) * 64;
    const int nslab = K / BK;

    float acc[2][8][4];
#pragma unroll
    for (int i = 0; i < 2; i++)
#pragma unroll
        for (int j = 0; j < 8; j++)
#pragma unroll
            for (int q = 0; q < 4; q++) acc[i][j][q] = 0.f;

    hg_prefetch(Ah, Al, lda, Bh, Bl, ldb, 0, sb, tid, m0, n0);
    CP_COMMIT();
    hg_prefetch(Ah, Al, lda, Bh, Bl, ldb, BK, sb + STAGE, tid, m0, n0);
    CP_COMMIT();

    for (int s = 0; s < nslab; s++) {
        const int st = s & 1;
        if (s == nslab - 1) { CP_WAIT0(); } else { CP_WAIT1(); }
        __syncthreads();
        hg_compute(sb + st * STAGE, lane, wm, wn, acc);
        __syncthreads();
        if (s + 2 < nslab) {
            hg_prefetch(Ah, Al, lda, Bh, Bl, ldb, (s + 2) * BK,
                        sb + st * STAGE, tid, m0, n0);
            CP_COMMIT();
        }
    }

    const int r0 = m0 + wm + (lane >> 2);
    const int c0 = n0 + wn + (lane & 3) * 2;
#pragma unroll
    for (int mi = 0; mi < 2; mi++) {
#pragma unroll
        for (int ni = 0; ni < 8; ni++) {
            int row = r0 + mi * 16;
            int col = c0 + ni * 8;
            const float* d = acc[mi][ni];
            float b0 = bias ? bias[col] : 0.f;
            float b1 = bias ? bias[col + 1] : 0.f;
            if (row < M) {
                C[(size_t)row * ldc + col]     = d[0] + b0;
                C[(size_t)row * ldc + col + 1] = d[1] + b1;
            }
            if (row + 8 < M) {
                C[(size_t)(row + 8) * ldc + col]     = d[2] + b0;
                C[(size_t)(row + 8) * ldc + col + 1] = d[3] + b1;
            }
        }
    }
}

// ---------------------------------------------------------------------------
// Fused encoder recurrence step, k-lane packed FFMA2 inner loop.
// acc lanes hold even/odd-k partial sums; reduced lo+hi at the end.
// grid (64 j-tiles of 16 cols, 2 dirs), 256 threads.
// ---------------------------------------------------------------------------
__global__ __launch_bounds__(256)
void enc_step_fused(int s,
                    const float* __restrict__ Wh_f,
                    const float* __restrict__ Wh_b,
                    const float* __restrict__ bh_f,
                    const float* __restrict__ bh_b) {
    constexpr int BK = 32;
    constexpr int LDA = BK + 4;   // 36 floats = 144B rows (16B aligned)
    __shared__ __align__(16) float As[64][LDA];
    __shared__ __align__(16) float Bs[48][LDA];
    const int tid = threadIdx.x;
    const int dir = blockIdx.y;
    const int j0 = blockIdx.x * 16;
    const float* hread = g_h[s & 1] + dir * (kB * kH);
    float* hwrite = g_h[(s + 1) & 1] + dir * (kB * kH);
    const float* Wh = dir ? Wh_b : Wh_f;
    const float* bh = dir ? bh_b : bh_f;
    const float* gxbase = dir ? g_gxb : g_gxf;
    const int gpos = dir ? (kS - 1 - s) : s;

    const int tm = (tid >> 4) << 2;   // 0..60, 4 rows/thread
    const int tn = tid & 15;          // gate column within 16-wide tile

    unsigned long long acc[4][3];
#pragma unroll
    for (int i = 0; i < 4; i++)
#pragma unroll
        for (int q = 0; q < 3; q++) acc[i][q] = 0ull;

    for (int k0 = 0; k0 < kH; k0 += BK) {
        // A: 64 rows x 32 k = 512 float4 chunks, 2 per thread
#pragma unroll
        for (int h = 0; h < 2; h++) {
            int id = tid + h * 256;
            int r = id >> 3, cc = (id & 7) << 2;
            *(float4*)&As[r][cc] =
                *(const float4*)(hread + (size_t)r * kH + k0 + cc);
        }
        // B: 48 gate-rows x 32 k = 384 float4 chunks
#pragma unroll
        for (int h = 0; h < 2; h++) {
            int id = tid + h * 256;
            if (id < 384) {
                int r = id >> 3, cc = (id & 7) << 2;
                int sec = r >> 4, wi = r & 15;
                *(float4*)&Bs[r][cc] = *(const float4*)(Wh +
                    (size_t)(sec * kH + j0 + wi) * kH + k0 + cc);
            }
        }
        __syncthreads();
#pragma unroll
        for (int k = 0; k < BK; k += 2) {
            unsigned long long b0 = *(const unsigned long long*)&Bs[tn][k];
            unsigned long long b1 = *(const unsigned long long*)&Bs[16 + tn][k];
            unsigned long long b2 = *(const unsigned long long*)&Bs[32 + tn][k];
#pragma unroll
            for (int i = 0; i < 4; i++) {
                unsigned long long a =
                    *(const unsigned long long*)&As[tm + i][k];
                fma2(acc[i][0], a, b0);
                fma2(acc[i][1], a, b1);
                fma2(acc[i][2], a, b2);
            }
        }
        __syncthreads();
    }

    const int j = j0 + tn;
    const float bhr = bh[j], bhz = bh[kH + j], bhn = bh[2 * kH + j];
#pragma unroll
    for (int i = 0; i < 4; i++) {
        int b = tm + i;
        float ghr = lo2(acc[i][0]) + hi2(acc[i][0]) + bhr;
        float ghz = lo2(acc[i][1]) + hi2(acc[i][1]) + bhz;
        float ghn = lo2(acc[i][2]) + hi2(acc[i][2]) + bhn;
        const float* gx = gxbase + ((size_t)gpos * kB + b) * kG;
        float r = 1.f / (1.f + expf(-(gx[j] + ghr)));
        float z = 1.f / (1.f + expf(-(gx[kH + j] + ghz)));
        float n = tanhf(gx[2 * kH + j] + r * ghn);
        float hold = hread[(size_t)b * kH + j];
        float h2 = (1.f - z) * n + z * hold;
        hwrite[(size_t)b * kH + j] = h2;
        g_enc[((size_t)b * kS + gpos) * (2 * kH) + dir * kH + j] = h2;
    }
}

// ---------------------------------------------------------------------------
// Small-M GEMM body (FFMA2)
// ---------------------------------------------------------------------------
__device__ __forceinline__
void gemm64_body(const float* __restrict__ A, int lda,
                 const float* __restrict__ Bm, int ldb,
                 const float* __restrict__ bias,
                 float* __restrict__ C, int ldc,
                 int K, int act, int nb) {
    constexpr int BK = 32;
    __shared__ __align__(16) float As[BK][64];
    __shared__ __align__(16) float Bs[BK][64];
    const int tid = threadIdx.x;
    const int bn = nb * 64;
    const int lr = tid >> 3;
    const int lc = (tid & 7) << 2;
    const int tm = (tid >> 4) << 2;
    const int tn = (tid & 15) << 2;

    unsigned long long acc[4][2];
#pragma unroll
    for (int i = 0; i < 4; i++) { acc[i][0] = 0ull; acc[i][1] = 0ull; }

    for (int k0 = 0; k0 < K; k0 += BK) {
#pragma unroll
        for (int h = 0; h < 2; h++) {
            int r = lr + h * 32;
            float4 v = *(const float4*)(A + (size_t)r * lda + k0 + lc);
            As[lc + 0][r] = v.x; As[lc + 1][r] = v.y;
            As[lc + 2][r] = v.z; As[lc + 3][r] = v.w;
            float4 w = *(const float4*)(Bm + (size_t)(bn + r) * ldb + k0 + lc);
            Bs[lc + 0][r] = w.x; Bs[lc + 1][r] = w.y;
            Bs[lc + 2][r] = w.z; Bs[lc + 3][r] = w.w;
        }
        __syncthreads();
#pragma unroll
        for (int k = 0; k < BK; k++) {
            float4 af = *(const float4*)&As[k][tm];
            unsigned long long aa[4];
            aa[0] = pk2(af.x); aa[1] = pk2(af.y);
            aa[2] = pk2(af.z); aa[3] = pk2(af.w);
            ulonglong2 bv = *(const ulonglong2*)&Bs[k][tn];
#pragma unroll
            for (int i = 0; i < 4; i++) {
                fma2(acc[i][0], aa[i], bv.x);
                fma2(acc[i][1], aa[i], bv.y);
            }
        }
        __syncthreads();
    }
#pragma unroll
    for (int i = 0; i < 4; i++) {
        int col = bn + tn;
        float4 v;
        v.x = lo2(acc[i][0]); v.y = hi2(acc[i][0]);
        v.z = lo2(acc[i][1]); v.w = hi2(acc[i][1]);
        if (bias) {
            v.x += bias[col + 0]; v.y += bias[col + 1];
            v.z += bias[col + 2]; v.w += bias[col + 3];
        }
        if (act == 1) {
            v.x = tanhf(v.x); v.y = tanhf(v.y);
            v.z = tanhf(v.z); v.w = tanhf(v.w);
        }
        *(float4*)(C + (size_t)(tm + i) * ldc + col) = v;
    }
}

__global__ __launch_bounds__(256)
void gemm64(const float* __restrict__ A, int lda,
            const float* __restrict__ Bm, int ldb,
            const float* __restrict__ bias,
            float* __restrict__ C, int ldc, int K, int act) {
    gemm64_body(A, lda, Bm, ldb, bias, C, ldc, K, act, blockIdx.x);
}

// Decoder pre-attention GEMMs, K-split 2: hp (32 blocks) + ghd (96 blocks)
__global__ __launch_bounds__(256)
void dec_pre_gemm(const float* __restrict__ W_attn,
                  const float* __restrict__ Wh_d,
                  const float* __restrict__ bh_d) {
    int x = blockIdx.x;
    if (x < 32) {
        int ks = x >> 4, nb = x & 15;
        gemm64_body(g_hdec + ks * 512, kH, W_attn + ks * 512, kG, nullptr,
                    g_hp + (size_t)ks * kB * kH, kH, 512, 0, nb);
    } else {
        int i = x - 32;
        int ks = i / 48, nb = i % 48;
        gemm64_body(g_hdec + ks * 512, kH, Wh_d + ks * 512, kH,
                    ks == 0 ? bh_d : nullptr,
                    g_ghd + (size_t)ks * kB * kG, kG, 512, 0, nb);
    }
}

// ---------------------------------------------------------------------------
__global__ void hcat_kernel() {
    int idx = blockIdx.x * blockDim.x + threadIdx.x;
    if (idx >= 2 * kB * kH) return;
    int dir = idx / (kB * kH);
    int rem = idx - dir * (kB * kH);
    int b = rem / kH, j = rem - b * kH;
    g_hcat[(size_t)b * 2 * kH + dir * kH + j] = g_h[0][idx];
}

// ---------------------------------------------------------------------------
// Fully fused decoder step (512 threads): scores -> softmax -> context w
// -> gxw = a @ encWi -> GRU gate. One block per batch element.
// ---------------------------------------------------------------------------
__global__ __launch_bounds__(512)
void attn_step_fused(const int* __restrict__ src,
                     const float* __restrict__ v_attn,
                     const float* __restrict__ gxet_t,
                     float* __restrict__ feat_t) {
    int b = blockIdx.x;
    __shared__ float sc[kS];
    __shared__ float sgxw[kG];
    int tid = threadIdx.x, warp = tid >> 5, lane = tid & 31;
    const float* hp0 = g_hp + (size_t)b * kH;
    const float* hp1 = g_hp + (size_t)kB * kH + (size_t)b * kH;

    // 1. attention scores (16 warps cover 48 source positions)
    for (int s = warp; s < kS; s += 16) {
        const float* ep = g_encproj + ((size_t)b * kS + s) * kH;
        float p = 0.f;
        for (int j = lane; j < kH; j += 32)
            p += v_attn[j] * tanhf(hp0[j] + hp1[j] + ep[j]);
#pragma unroll
        for (int o = 16; o; o >>= 1) p += __shfl_xor_sync(0xffffffffu, p, o);
        if (lane == 0) sc[s] = (src[s * kB + b] != kPAD) ? p : -1e10f;
    }
    __syncthreads();

    // 2. softmax over S=48
    if (tid < 32) {
        float v1 = sc[tid];
        float v2 = (tid + 32 < kS) ? sc[tid + 32] : -1e30f;
        float mx = fmaxf(v1, v2);
#pragma unroll
        for (int o = 16; o; o >>= 1) mx = fmaxf(mx, __shfl_xor_sync(0xffffffffu, mx, o));
        float e1 = expf(v1 - mx);
        float e2 = (tid + 32 < kS) ? expf(v2 - mx) : 0.f;
        float sm = e1 + e2;
#pragma unroll
        for (int o = 16; o; o >>= 1) sm += __shfl_xor_sync(0xffffffffu, sm, o);
        float inv = 1.f / sm;
        sc[tid] = e1 * inv;
        if (tid + 32 < kS) sc[tid + 32] = e2 * inv;
    }
    __syncthreads();

    // 3a. context w = a @ enc
    for (int c4 = tid; c4 < 2 * kH / 4; c4 += 512) {
        float4 acc = make_float4(0.f, 0.f, 0.f, 0.f);
        const float4* base = (const float4*)(g_enc + (size_t)b * kS * 2 * kH) + c4;
#pragma unroll 8
        for (int s = 0; s < kS; s++) {
            float a = sc[s];
            float4 e = base[s * (2 * kH / 4)];
            acc.x += a * e.x; acc.y += a * e.y;
            acc.z += a * e.z; acc.w += a * e.w;
        }
        ((float4*)(feat_t + (size_t)b * kF + kH))[c4] = acc;
    }
    // 3b. gxw = a @ encWi  (3072 cols -> smem)
    for (int c4 = tid; c4 < kG / 4; c4 += 512) {
        float4 acc = make_float4(0.f, 0.f, 0.f, 0.f);
        const float4* base = (const float4*)(g_encWi + (size_t)b * kS * kG) + c4;
#pragma unroll 8
        for (int s = 0; s < kS; s++) {
            float a = sc[s];
            float4 e = base[s * (kG / 4)];
            acc.x += a * e.x; acc.y += a * e.y;
            acc.z += a * e.z; acc.w += a * e.w;
        }
        *(float4*)(sgxw + c4 * 4) = acc;
    }
    __syncthreads();

    // 4. GRU gate -> h2
    const float* q0 = g_ghd + (size_t)b * kG;
    const float* q1 = g_ghd + (size_t)kB * kG + (size_t)b * kG;
    const float* gx = gxet_t + (size_t)b * kG;
    for (int j = tid; j < kH; j += 512) {
        float h = g_hdec[(size_t)b * kH + j];
        float xr = gx[j] + sgxw[j];
        float xz = gx[kH + j] + sgxw[kH + j];
        float xn = gx[2 * kH + j] + sgxw[2 * kH + j];
        float ghr = q0[j] + q1[j];
        float ghz = q0[kH + j] + q1[kH + j];
        float ghn = q0[2 * kH + j] + q1[2 * kH + j];
        float r = 1.f / (1.f + expf(-(xr + ghr)));
        float z = 1.f / (1.f + expf(-(xz + ghz)));
        float n = tanhf(xn + r * ghn);
        float h2 = (1.f - z) * n + z * h;
        g_hdec[(size_t)b * kH + j] = h2;
        feat_t[(size_t)b * kF + j] = h2;
    }
}

// ---------------------------------------------------------------------------
// Host orchestration (two-stream fork/join, graph-capturable)
// ---------------------------------------------------------------------------
extern "C" void kernel_launch(void* const* d_in, const int* in_sizes, int n_in,
                              void* d_out, int out_size) {
    const int*   src     = (const int*)d_in[0];
    const int*   trg     = (const int*)d_in[1];
    const float* emb_enc = (const float*)d_in[2];
    const float* Wi_f    = (const float*)d_in[3];
    const float* Wh_f    = (const float*)d_in[4];
    const float* bi_f    = (const float*)d_in[5];
    const float* bh_f    = (const float*)d_in[6];
    const float* Wi_b    = (const float*)d_in[7];
    const float* Wh_b    = (const float*)d_in[8];
    const float* bi_b    = (const float*)d_in[9];
    const float* bh_b    = (const float*)d_in[10];
    const float* W_fc    = (const float*)d_in[11];
    const float* b_fc    = (const float*)d_in[12];
    const float* W_attn  = (const float*)d_in[13];
    const float* b_attn  = (const float*)d_in[14];
    const float* v_attn  = (const float*)d_in[15];
    const float* emb_dec = (const float*)d_in[16];
    const float* Wi_d    = (const float*)d_in[17];
    const float* Wh_d    = (const float*)d_in[18];
    const float* bi_d    = (const float*)d_in[19];
    const float* bh_d    = (const float*)d_in[20];
    const float* W_out   = (const float*)d_in[21];
    const float* b_out   = (const float*)d_in[22];
    float* out = (float*)d_out;

    float *p_enc, *p_ep, *p_encWi, *p_hcat, *p_hdec, *p_gxet, *p_feat,
          *p_gxf, *p_gxb;
    __nv_bfloat16 *p_Ahi, *p_Alo, *p_Bhi, *p_Blo, *p_Ehi, *p_Elo;
    __nv_bfloat16 *p_Wifh, *p_Wifl, *p_Wibh, *p_Wibl;
    __nv_bfloat16 *p_Widh, *p_Widl, *p_Wah, *p_Wal, *p_Ench, *p_Encl;
    cudaGetSymbolAddress((void**)&p_enc, g_enc);
    cudaGetSymbolAddress((void**)&p_ep, g_encproj);
    cudaGetSymbolAddress((void**)&p_encWi, g_encWi);
    cudaGetSymbolAddress((void**)&p_hcat, g_hcat);
    cudaGetSymbolAddress((void**)&p_hdec, g_hdec);
    cudaGetSymbolAddress((void**)&p_gxet, g_gxet);
    cudaGetSymbolAddress((void**)&p_feat, g_feat);
    cudaGetSymbolAddress((void**)&p_gxf, g_gxf);
    cudaGetSymbolAddress((void**)&p_gxb, g_gxb);
    cudaGetSymbolAddress((void**)&p_Ahi, g_Ahi);
    cudaGetSymbolAddress((void**)&p_Alo, g_Alo);
    cudaGetSymbolAddress((void**)&p_Bhi, g_Bhi);
    cudaGetSymbolAddress((void**)&p_Blo, g_Blo);
    cudaGetSymbolAddress((void**)&p_Ehi, g_Ehi);
    cudaGetSymbolAddress((void**)&p_Elo, g_Elo);
    cudaGetSymbolAddress((void**)&p_Wifh, g_Wifh);
    cudaGetSymbolAddress((void**)&p_Wifl, g_Wifl);
    cudaGetSymbolAddress((void**)&p_Wibh, g_Wibh);
    cudaGetSymbolAddress((void**)&p_Wibl, g_Wibl);
    cudaGetSymbolAddress((void**)&p_Widh, g_Widh);
    cudaGetSymbolAddress((void**)&p_Widl, g_Widl);
    cudaGetSymbolAddress((void**)&p_Wah, g_Wah);
    cudaGetSymbolAddress((void**)&p_Wal, g_Wal);
    cudaGetSymbolAddress((void**)&p_Ench, g_Ench);
    cudaGetSymbolAddress((void**)&p_Encl, g_Encl);

    static cudaStream_t s1 = nullptr;
    static cudaEvent_t evFork = nullptr, evJoin = nullptr;
    if (s1 == nullptr) {
        cudaStreamCreateWithFlags(&s1, cudaStreamNonBlocking);
        cudaEventCreateWithFlags(&evFork, cudaEventDisableTiming);
        cudaEventCreateWithFlags(&evJoin, cudaEventDisableTiming);
        cudaFuncSetAttribute(hgemm,
                             cudaFuncAttributeMaxDynamicSharedMemorySize,
                             outg::SMEM_SZ);
    }

    // fork side stream off the capture stream
    cudaEventRecord(evFork, 0);
    cudaStreamWaitEvent(s1, evFork, 0);

    // --- main stream: encoder-critical path ---
    init_kernel<<<((size_t)kB * kV + 255) / 256, 256>>>(out);
    enc_embed_kernel<<<kME, 128>>>(src, emb_enc);
    {
        size_t n4 = (size_t)kG * kE / 4;
        cvt_split4<<<(unsigned)((n4 + 255) / 256), 256>>>(
            (const float4*)Wi_f, (__nv_bfloat162*)p_Wifh,
            (__nv_bfloat162*)p_Wifl, n4);
        cvt_split4<<<(unsigned)((n4 + 255) / 256), 256>>>(
            (const float4*)Wi_b, (__nv_bfloat162*)p_Wibh,
            (__nv_bfloat162*)p_Wibl, n4);
    }
    // --- side stream: decoder-prep + big weight conversions ---
    dec_embed_all<<<kMR, 128, 0, s1>>>(trg, emb_dec);
    // --- main: input-gate GEMMs ---
    hgemm<<<dim3(kME / 128, kG / 128), 256, outg::SMEM_SZ>>>(
        p_Ehi, p_Elo, kE, p_Wifh, p_Wifl, kE, bi_f, p_gxf, kG, kME, kE);
    hgemm<<<dim3(kME / 128, kG / 128), 256, outg::SMEM_SZ>>>(
        p_Ehi, p_Elo, kE, p_Wibh, p_Wibl, kE, bi_b, p_gxb, kG, kME, kE);
    // --- side stream continues ---
    {
        size_t n4 = (size_t)kG * kXW / 4;
        cvt_split4<<<(unsigned)((n4 + 255) / 256), 256, 0, s1>>>(
            (const float4*)Wi_d, (__nv_bfloat162*)p_Widh,
            (__nv_bfloat162*)p_Widl, n4);
        n4 = (size_t)kH * kG / 4;
        cvt_split4<<<(unsigned)((n4 + 255) / 256), 256, 0, s1>>>(
            (const float4*)W_attn, (__nv_bfloat162*)p_Wah,
            (__nv_bfloat162*)p_Wal, n4);
        hgemm<<<dim3(kMP / 128, kG / 128), 256, outg::SMEM_SZ, s1>>>(
            p_Ahi + 3 * kH, p_Alo + 3 * kH, kF, p_Widh, p_Widl, kXW, bi_d,
            p_gxet, kG, kMR, kE);
        n4 = (size_t)kV * kF / 4;
        cvt_split4<<<(unsigned)((n4 + 255) / 256), 256, 0, s1>>>(
            (const float4*)W_out, (__nv_bfloat162*)p_Bhi,
            (__nv_bfloat162*)p_Blo, n4);
    }
    cudaEventRecord(evJoin, s1);

    // --- main: encoder recurrence (overlaps side stream) ---
    for (int s = 0; s < kS; s++)
        enc_step_fused<<<dim3(64, 2), 256>>>(s, Wh_f, Wh_b, bh_f, bh_b);

    // decoder init hidden
    hcat_kernel<<<(2 * kB * kH) / 256, 256>>>();
    gemm64<<<kH / 64, 256>>>(p_hcat, 2 * kH, W_fc, 2 * kH, b_fc,
                             p_hdec, kH, 2 * kH, 1);

    // encoder split + attention projection + encWi (needs side stream)
    {
        size_t n4 = (size_t)kME * 2 * kH / 4;
        cvt_split4<<<(unsigned)((n4 + 255) / 256), 256>>>(
            (const float4*)p_enc, (__nv_bfloat162*)p_Ench,
            (__nv_bfloat162*)p_Encl, n4);
        cudaStreamWaitEvent(0, evJoin, 0);
        hgemm<<<dim3(kME / 128, kH / 128), 256, outg::SMEM_SZ>>>(
            p_Ench, p_Encl, 2 * kH, p_Wah + kH, p_Wal + kH, kG, b_attn,
            p_ep, kH, kME, 2 * kH);
        hgemm<<<dim3(kME / 128, kG / 128), 256, outg::SMEM_SZ>>>(
            p_Ench, p_Encl, 2 * kH, p_Widh + kE, p_Widl + kE, kXW,
            (const float*)nullptr, p_encWi, kG, kME, 2 * kH);
    }

    // decoder loop: 2 launches per step
    for (int t = 0; t < kT - 1; t++) {
        float* feat_t = p_feat + (size_t)t * kB * kF;
        dec_pre_gemm<<<128, 256>>>(W_attn, Wh_d, bh_d);
        attn_step_fused<<<kB, 512>>>(src, v_attn,
                                     p_gxet + (size_t)t * kB * kG, feat_t);
    }

    // split-convert features, HMMA output projection
    {
        size_t n = (size_t)kMP * (3 * kH) / 4;
        cvt_feat_split<<<(unsigned)((n + 255) / 256), 256>>>();
        hgemm<<<dim3(kMP / 128, kV / 128), 256, outg::SMEM_SZ>>>(
            p_Ahi, p_Alo, kF, p_Bhi, p_Blo, kF, b_out,
            out + (size_t)kB * kV, kV, kMR, kF);
    }
}